// round 6
// baseline (speedup 1.0000x reference)
#include <cuda_runtime.h>
#include <cuda_bf16.h>
#include <mma.h>
#include <math.h>

using namespace nvcuda;

#define BBATCH 256
#define LLEN   128
#define KNBR   6
#define FAD    39
#define FBD    10
#define DDIM   128
#define NRAD   3
#define NTS    2
#define NEGV   (-9e8f)

static const int M_ATOM = BBATCH * LLEN;          // 32768

// ---------------- scratch (device globals; no allocations) ----------------
__device__ __align__(256) float g_h    [32768 * 128];
__device__ __align__(256) float g_act  [32768 * 128];
__device__ __align__(256) float g_ctx  [32768 * 128];
__device__ __align__(256) float g_P    [32768 * 128];
__device__ __align__(256) float g_atomT[32768 * 128];
__device__ __align__(256) float g_bondT[32768 * 128];
__device__ __align__(256) float g_A64  [32768 * 64];
__device__ __align__(256) float g_B32  [32768 * 32];
__device__ __align__(256) float g_gi   [32768 * 384];
__device__ __align__(256) float g_gh   [32768 * 384];
__device__ __align__(256) float g_sc   [32768];
__device__ __align__(256) float g_sn   [32768];
__device__ __align__(256) float g_sumw [32768];
__device__ __align__(256) float g_Wa   [64 * 128];
__device__ __align__(256) float g_Wt   [64 * 128];
__device__ __align__(256) float g_Wb   [32 * 128];
__device__ __align__(256) float g_molf [256 * 128];
__device__ __align__(256) float g_pred [256];

// ---------------- bf16 hi/lo split of two floats ----------------
__device__ __forceinline__ void f2bf_split2(float x, float y,
                                            __nv_bfloat162& hi, __nv_bfloat162& lo)
{
    __nv_bfloat16 hx = __float2bfloat16(x);
    __nv_bfloat16 hy = __float2bfloat16(y);
    hi = __nv_bfloat162(hx, hy);
    lo = __nv_bfloat162(__float2bfloat16(x - __bfloat162float(hx)),
                        __float2bfloat16(y - __bfloat162float(hy)));
}

// ============== bf16x3 split GEMM, BM=128/BN=128/BK=32, 2-stage pipeline ===
// C[M,N] = epilogue(A[M,K] @ B)
// BL=0: W stored [K,N] row-major.  BL=1: W stored [N,K] row-major (B = W^T).
// MODE: 0 raw, 1 lrelu(x+bias[n]), 3 elu(x + rowscale[m]*bias[n])
// Requires: M%128==0, grid.y = N/128, K%32==0, 16B-aligned pointers.
// Dynamic smem: 2 stages of (A:128x40 hi/lo bf16, B tile hi/lo bf16).
template<int BL, int MODE>
__global__ void __launch_bounds__(256) gemm_bf16x3_k(
    const float* __restrict__ A, const float* __restrict__ W,
    const float* __restrict__ bias, const float* __restrict__ rowscale,
    float* __restrict__ C, int M, int K, int N)
{
    constexpr int LDA = 40;                              // bf16 elems
    constexpr int LDB = (BL == 0) ? 136 : 40;
    constexpr int A_ELEMS = 128 * LDA;                   // per hi or lo
    constexpr int B_ELEMS = (BL == 0) ? 32 * 136 : 128 * 40;
    constexpr int STG_ELEMS = 2 * A_ELEMS + 2 * B_ELEMS; // bf16 elems per stage

    extern __shared__ __align__(16) char dynbuf[];

    const int tid  = threadIdx.x;
    const int warp = tid >> 5;
    const int wm = warp & 3;                             // 4 warps in M (32 rows each)
    const int wn = warp >> 2;                            // 2 warps in N (64 cols each)
    const int m0 = blockIdx.x * 128, n0 = blockIdx.y * 128;

    wmma::fragment<wmma::accumulator, 16, 16, 16, float> acc[2][4];
#pragma unroll
    for (int mi = 0; mi < 2; ++mi)
#pragma unroll
        for (int ni = 0; ni < 4; ++ni) wmma::fill_fragment(acc[mi][ni], 0.f);

    const int nk = K >> 5;
    float4 ra[4], rb[4];

    // ---- tile loaders (global -> regs) ----
    auto load_tile = [&](int kt) {
        int k0 = kt << 5;
#pragma unroll
        for (int t = 0; t < 4; ++t) {
            int i = tid + t * 256;                       // [0,1024)
            int row = i >> 3, c4 = i & 7;
            ra[t] = *(const float4*)(A + (size_t)(m0 + row) * K + k0 + c4 * 4);
        }
#pragma unroll
        for (int t = 0; t < 4; ++t) {
            int i = tid + t * 256;
            if (BL == 0) {
                int r = i >> 5, c4 = i & 31;             // 32 x 128
                rb[t] = *(const float4*)(W + (size_t)(k0 + r) * N + n0 + c4 * 4);
            } else {
                int r = i >> 3, c4 = i & 7;              // 128 x 32
                rb[t] = *(const float4*)(W + (size_t)(n0 + r) * K + k0 + c4 * 4);
            }
        }
    };
    // ---- regs -> smem stage (with bf16 hi/lo split) ----
    auto store_tile = [&](int stage) {
        __nv_bfloat16* Ah = (__nv_bfloat16*)dynbuf + (size_t)stage * STG_ELEMS;
        __nv_bfloat16* Al = Ah + A_ELEMS;
        __nv_bfloat16* Bh = Al + A_ELEMS;
        __nv_bfloat16* Bl = Bh + B_ELEMS;
#pragma unroll
        for (int t = 0; t < 4; ++t) {
            int i = tid + t * 256;
            int row = i >> 3, c4 = i & 7;
            __nv_bfloat162 h0, l0, h1, l1;
            f2bf_split2(ra[t].x, ra[t].y, h0, l0);
            f2bf_split2(ra[t].z, ra[t].w, h1, l1);
            __nv_bfloat162* ph = (__nv_bfloat162*)(Ah + row * LDA + c4 * 4);
            __nv_bfloat162* pl = (__nv_bfloat162*)(Al + row * LDA + c4 * 4);
            ph[0] = h0; ph[1] = h1; pl[0] = l0; pl[1] = l1;
        }
#pragma unroll
        for (int t = 0; t < 4; ++t) {
            int i = tid + t * 256;
            int r, c;
            if (BL == 0) { r = i >> 5; c = (i & 31) * 4; }
            else         { r = i >> 3; c = (i & 7) * 4; }
            __nv_bfloat162 h0, l0, h1, l1;
            f2bf_split2(rb[t].x, rb[t].y, h0, l0);
            f2bf_split2(rb[t].z, rb[t].w, h1, l1);
            __nv_bfloat162* ph = (__nv_bfloat162*)(Bh + r * LDB + c);
            __nv_bfloat162* pl = (__nv_bfloat162*)(Bl + r * LDB + c);
            ph[0] = h0; ph[1] = h1; pl[0] = l0; pl[1] = l1;
        }
    };
    // ---- MMA over one smem stage ----
    auto compute = [&](int stage) {
        const __nv_bfloat16* Ah = (const __nv_bfloat16*)dynbuf + (size_t)stage * STG_ELEMS;
        const __nv_bfloat16* Al = Ah + A_ELEMS;
        const __nv_bfloat16* Bh = Al + A_ELEMS;
        const __nv_bfloat16* Bl = Bh + B_ELEMS;
#pragma unroll
        for (int kc = 0; kc < 32; kc += 16) {
            wmma::fragment<wmma::matrix_a, 16, 16, 16, __nv_bfloat16, wmma::row_major> ah[2], al[2];
#pragma unroll
            for (int mi = 0; mi < 2; ++mi) {
                wmma::load_matrix_sync(ah[mi], Ah + (wm * 32 + mi * 16) * LDA + kc, LDA);
                wmma::load_matrix_sync(al[mi], Al + (wm * 32 + mi * 16) * LDA + kc, LDA);
            }
#pragma unroll
            for (int ni = 0; ni < 4; ++ni) {
                if (BL == 0) {
                    wmma::fragment<wmma::matrix_b, 16, 16, 16, __nv_bfloat16, wmma::row_major> bh, bl;
                    wmma::load_matrix_sync(bh, Bh + kc * LDB + wn * 64 + ni * 16, LDB);
                    wmma::load_matrix_sync(bl, Bl + kc * LDB + wn * 64 + ni * 16, LDB);
#pragma unroll
                    for (int mi = 0; mi < 2; ++mi) {
                        wmma::mma_sync(acc[mi][ni], ah[mi], bl, acc[mi][ni]);
                        wmma::mma_sync(acc[mi][ni], al[mi], bh, acc[mi][ni]);
                        wmma::mma_sync(acc[mi][ni], ah[mi], bh, acc[mi][ni]);
                    }
                } else {
                    wmma::fragment<wmma::matrix_b, 16, 16, 16, __nv_bfloat16, wmma::col_major> bh, bl;
                    wmma::load_matrix_sync(bh, Bh + (wn * 64 + ni * 16) * LDB + kc, LDB);
                    wmma::load_matrix_sync(bl, Bl + (wn * 64 + ni * 16) * LDB + kc, LDB);
#pragma unroll
                    for (int mi = 0; mi < 2; ++mi) {
                        wmma::mma_sync(acc[mi][ni], ah[mi], bl, acc[mi][ni]);
                        wmma::mma_sync(acc[mi][ni], al[mi], bh, acc[mi][ni]);
                        wmma::mma_sync(acc[mi][ni], ah[mi], bh, acc[mi][ni]);
                    }
                }
            }
        }
    };

    // ---- pipelined main loop ----
    load_tile(0);
    store_tile(0);
    __syncthreads();
    for (int kt = 0; kt < nk; ++kt) {
        if (kt + 1 < nk) load_tile(kt + 1);
        compute(kt & 1);
        if (kt + 1 < nk) store_tile((kt + 1) & 1);
        __syncthreads();
    }

    // ---- epilogue via smem staging (reuses dynbuf) ----
    float* Cs = (float*)dynbuf;                           // 128 x 136
#pragma unroll
    for (int mi = 0; mi < 2; ++mi)
#pragma unroll
        for (int ni = 0; ni < 4; ++ni)
            wmma::store_matrix_sync(Cs + (wm * 32 + mi * 16) * 136 + wn * 64 + ni * 16,
                                    acc[mi][ni], 136, wmma::mem_row_major);
    __syncthreads();
#pragma unroll
    for (int t = 0; t < 16; ++t) {
        int i = tid + t * 256;                            // [0,4096)
        int row = i >> 5, c4 = i & 31;
        float4 v = *(float4*)(Cs + row * 136 + c4 * 4);
        int n = n0 + c4 * 4;
        if (MODE == 1) {
            v.x += bias[n];     v.y += bias[n + 1];  v.z += bias[n + 2];  v.w += bias[n + 3];
            v.x = v.x > 0.f ? v.x : 0.01f * v.x;
            v.y = v.y > 0.f ? v.y : 0.01f * v.y;
            v.z = v.z > 0.f ? v.z : 0.01f * v.z;
            v.w = v.w > 0.f ? v.w : 0.01f * v.w;
        } else if (MODE == 3) {
            float rs = rowscale[m0 + row];
            v.x += rs * bias[n];     v.y += rs * bias[n + 1];
            v.z += rs * bias[n + 2]; v.w += rs * bias[n + 3];
            v.x = v.x > 0.f ? v.x : expm1f(v.x);
            v.y = v.y > 0.f ? v.y : expm1f(v.y);
            v.z = v.z > 0.f ? v.z : expm1f(v.z);
            v.w = v.w > 0.f ? v.w : expm1f(v.w);
        }
        *(float4*)(C + (size_t)(m0 + row) * N + n) = v;
    }
}

// ---------------- block reductions ----------------
__device__ __forceinline__ float blk_sum(float v, float* red, int j)
{
#pragma unroll
    for (int o = 16; o > 0; o >>= 1) v += __shfl_down_sync(0xffffffffu, v, o);
    if ((j & 31) == 0) red[j >> 5] = v;
    __syncthreads();
    v = red[0] + red[1] + red[2] + red[3];
    __syncthreads();
    return v;
}
__device__ __forceinline__ float blk_max(float v, float* red, int j)
{
#pragma unroll
    for (int o = 16; o > 0; o >>= 1) v = fmaxf(v, __shfl_down_sync(0xffffffffu, v, o));
    if ((j & 31) == 0) red[j >> 5] = v;
    __syncthreads();
    v = fmaxf(fmaxf(red[0], red[1]), fmaxf(red[2], red[3]));
    __syncthreads();
    return v;
}

// ---------------- padding kernels ----------------
__global__ void pad_atom_k(const float* __restrict__ atom, float* __restrict__ out)
{
    int r = blockIdx.x, t = threadIdx.x;
    out[(size_t)r * 64 + t] = (t < FAD) ? atom[(size_t)r * FAD + t] : 0.f;
}
__global__ void pad_bond_k(const float* __restrict__ bond, float* __restrict__ out)
{
    int r = blockIdx.x, t = threadIdx.x;
    out[(size_t)r * 32 + t] = (t < FBD) ? bond[(size_t)r * FBD + t] : 0.f;
}
__global__ void pad_w_k(const float* __restrict__ w, float* __restrict__ out,
                        int Ksrc, int off)
{
    int r = blockIdx.x, j = threadIdx.x;
    out[r * 128 + j] = (r < Ksrc) ? w[(off + r) * 128 + j] : 0.f;
}

// ---------------- fused d=0 attention ----------------
__global__ void attn0_k(const float* __restrict__ h, const float* __restrict__ atomT,
                        const float* __restrict__ bondT, const int* __restrict__ adl,
                        const int* __restrict__ bdl, const float* __restrict__ nbias,
                        const float* __restrict__ aw, const float* __restrict__ ab,
                        float* __restrict__ wnbr, float* __restrict__ sumw)
{
    int bl = blockIdx.x, j = threadIdx.x;
    int bbase = (bl >> 7) << 7;
    __shared__ float red[4];
    const int base = bl * KNBR;
    float sc = blk_sum(h[(size_t)bl * DDIM + j] * aw[j], red, j);
    float aw2 = aw[DDIM + j];
    float ab0 = ab[0];
    float nb  = nbias[j];
    float v[KNBR], s[KNBR], msk[KNBR];
#pragma unroll
    for (int k = 0; k < KNBR; ++k) {
        int ai = adl[base + k], bi = bdl[base + k];
        float x = atomT[(size_t)(bbase + ai) * DDIM + j]
                + bondT[(size_t)(bbase + bi) * DDIM + j] + nb;
        v[k] = x > 0.f ? x : 0.01f * x;
        msk[k] = (ai == LLEN - 1) ? 0.f : 1.f;
    }
#pragma unroll
    for (int k = 0; k < KNBR; ++k) {
        float d = blk_sum(v[k] * aw2, red, j);
        float sco = sc + d + ab0;
        sco = sco > 0.f ? sco : 0.01f * sco;
        if (msk[k] == 0.f) sco += NEGV;
        s[k] = sco;
    }
    float mx = -1e30f;
#pragma unroll
    for (int k = 0; k < KNBR; ++k) mx = fmaxf(mx, s[k]);
    float ss = 0.f;
#pragma unroll
    for (int k = 0; k < KNBR; ++k) { s[k] = expf(s[k] - mx); ss += s[k]; }
    float acc = 0.f, sw = 0.f;
#pragma unroll
    for (int k = 0; k < KNBR; ++k) {
        float w = s[k] / ss * msk[k];
        acc = fmaf(w, v[k], acc);
        sw += w;
    }
    wnbr[(size_t)bl * DDIM + j] = acc;
    if (j == 0) sumw[bl] = sw;
}

// ---------------- two dots in one pass ----------------
__global__ void dot2_k(const float* __restrict__ X, const float* __restrict__ w1,
                       const float* __restrict__ w2, float* __restrict__ o1,
                       float* __restrict__ o2)
{
    int row = blockIdx.x, j = threadIdx.x;
    __shared__ float red[4];
    float x = X[(size_t)row * DDIM + j];
    float a = blk_sum(x * w1[j], red, j);
    float b = blk_sum(x * w2[j], red, j);
    if (j == 0) { o1[row] = a; o2[row] = b; }
}
__global__ void dot128_k(const float* __restrict__ X, const float* __restrict__ v,
                         float* __restrict__ out)
{
    int row = blockIdx.x, j = threadIdx.x;
    __shared__ float red[4];
    float p = blk_sum(X[(size_t)row * DDIM + j] * v[j], red, j);
    if (j == 0) out[row] = p;
}

// ---------------- d>=1 attention ----------------
__global__ void attn_k(const float* __restrict__ sc, const float* __restrict__ sn,
                       const float* __restrict__ P, const int* __restrict__ adl,
                       const float* __restrict__ abp, const float* __restrict__ tb,
                       float* __restrict__ ctx)
{
    int bl = blockIdx.x;
    int b  = bl >> 7;
    int j  = threadIdx.x;
    __shared__ float ws[KNBR];
    __shared__ float swsh;
    __shared__ int   rowidx[KNBR];
    if (j == 0) {
        float ab = abp[0];
        float s[KNBR], msk[KNBR];
        float mx = -1e30f;
#pragma unroll
        for (int k = 0; k < KNBR; ++k) {
            int id = adl[bl * KNBR + k];
            int src = b * LLEN + id;
            rowidx[k] = src;
            float sco = sc[bl] + sn[src] + ab;
            sco = sco > 0.f ? sco : 0.01f * sco;
            bool pad = (id == LLEN - 1);
            if (pad) sco += NEGV;
            msk[k] = pad ? 0.f : 1.f;
            s[k] = sco;
            mx = fmaxf(mx, sco);
        }
        float sum = 0.f;
#pragma unroll
        for (int k = 0; k < KNBR; ++k) { s[k] = expf(s[k] - mx); sum += s[k]; }
        float sw = 0.f;
#pragma unroll
        for (int k = 0; k < KNBR; ++k) { ws[k] = s[k] / sum * msk[k]; sw += ws[k]; }
        swsh = sw;
    }
    __syncthreads();
    float c = 0.f;
#pragma unroll
    for (int k = 0; k < KNBR; ++k)
        c = fmaf(ws[k], P[(size_t)rowidx[k] * DDIM + j], c);
    c += swsh * tb[j];
    c = c > 0.f ? c : expm1f(c);
    ctx[(size_t)bl * DDIM + j] = c;
}

// ---------------- GRU gate fusion (optional direct h output) ----------------
__global__ void gru_gate_k(const float* __restrict__ gi, const float* __restrict__ gh,
                           const float* __restrict__ bih, const float* __restrict__ bhh,
                           float* __restrict__ h, float* __restrict__ act,
                           float* __restrict__ out_h, int M)
{
    int idx = blockIdx.x * blockDim.x + threadIdx.x;
    if (idx >= M * DDIM) return;
    int m = idx >> 7, j = idx & 127;
    size_t base = (size_t)m * 384;
    float ir = gi[base + j] + bih[j];
    float iz = gi[base + 128 + j] + bih[128 + j];
    float in = gi[base + 256 + j] + bih[256 + j];
    float hr = gh[base + j] + bhh[j];
    float hz = gh[base + 128 + j] + bhh[128 + j];
    float hn = gh[base + 256 + j] + bhh[256 + j];
    float r = 1.f / (1.f + expf(-(ir + hr)));
    float z = 1.f / (1.f + expf(-(iz + hz)));
    float n = tanhf(in + r * hn);
    float hv = h[idx];
    float hnew = (1.f - z) * n + z * hv;
    h[idx] = hnew;
    act[idx] = hnew > 0.f ? hnew : 0.f;
    if (out_h) out_h[idx] = hnew;
}

// ---------------- masked sum over atoms ----------------
__global__ void molsum_k(const float* __restrict__ act, const float* __restrict__ mask,
                         float* __restrict__ molf)
{
    int b = blockIdx.x, j = threadIdx.x;
    float s = 0.f;
    for (int l = 0; l < LLEN; ++l)
        s = fmaf(act[((size_t)b * LLEN + l) * DDIM + j], mask[b * LLEN + l], s);
    molf[b * DDIM + j] = s;
}

// ---------------- per-molecule mol-attention + GRU ----------------
__global__ void mol_k(const float* __restrict__ molf_in, const float* __restrict__ mask,
                      const float* __restrict__ snm, const float* __restrict__ Pm,
                      const float* __restrict__ maw, const float* __restrict__ mab,
                      const float* __restrict__ matt_b,
                      const float* __restrict__ wih, const float* __restrict__ whh,
                      const float* __restrict__ bih, const float* __restrict__ bhh,
                      const float* __restrict__ outw, const float* __restrict__ outb,
                      float* __restrict__ molf_out, float* __restrict__ pred)
{
    int b = blockIdx.x;
    int j = threadIdx.x;
    __shared__ float smolf[DDIM];
    __shared__ float w[LLEN];
    __shared__ float sctx[DDIM];
    __shared__ float red[4];
    smolf[j] = molf_in[b * DDIM + j];
    float mymask = mask[b * LLEN + j];
    float mysnm  = snm[b * LLEN + j];
    float mabv   = mab[0];
    float mybias = matt_b[j];

    for (int t = 0; t < NTS; ++t) {
        __syncthreads();
        float amj = fmaxf(smolf[j], 0.f);
        float scv = blk_sum(amj * maw[j], red, j);
        float sco = scv + mysnm + mabv;
        sco = sco > 0.f ? sco : 0.01f * sco;
        if (mymask == 0.f) sco += NEGV;
        float mx = blk_max(sco, red, j);
        float ev = expf(sco - mx);
        float ss = blk_sum(ev, red, j);
        float wj = ev / ss * mymask;
        w[j] = wj;
        float sumw = blk_sum(wj, red, j);
        __syncthreads();
        float c = 0.f;
#pragma unroll 4
        for (int l = 0; l < LLEN; ++l)
            c = fmaf(w[l], Pm[((size_t)b * LLEN + l) * DDIM + j], c);
        c += sumw * mybias;
        c = c > 0.f ? c : expm1f(c);
        sctx[j] = c;
        __syncthreads();
        float gi0 = bih[j], gi1 = bih[DDIM + j], gi2 = bih[2 * DDIM + j];
        float gh0 = bhh[j], gh1 = bhh[DDIM + j], gh2 = bhh[2 * DDIM + j];
        const float* wi0 = wih + (size_t)j * DDIM;
        const float* wi1 = wih + (size_t)(DDIM + j) * DDIM;
        const float* wi2 = wih + (size_t)(2 * DDIM + j) * DDIM;
        const float* wh0 = whh + (size_t)j * DDIM;
        const float* wh1 = whh + (size_t)(DDIM + j) * DDIM;
        const float* wh2 = whh + (size_t)(2 * DDIM + j) * DDIM;
#pragma unroll 4
        for (int k = 0; k < DDIM; ++k) {
            float ck = sctx[k], hk = smolf[k];
            gi0 = fmaf(ck, wi0[k], gi0);
            gi1 = fmaf(ck, wi1[k], gi1);
            gi2 = fmaf(ck, wi2[k], gi2);
            gh0 = fmaf(hk, wh0[k], gh0);
            gh1 = fmaf(hk, wh1[k], gh1);
            gh2 = fmaf(hk, wh2[k], gh2);
        }
        float r = 1.f / (1.f + expf(-(gi0 + gh0)));
        float z = 1.f / (1.f + expf(-(gi1 + gh1)));
        float n = tanhf(gi2 + r * gh2);
        float hnew = (1.f - z) * n + z * smolf[j];
        __syncthreads();
        smolf[j] = hnew;
    }
    __syncthreads();
    molf_out[b * DDIM + j] = smolf[j];
    float tot = blk_sum(smolf[j] * outw[j], red, j);
    if (j == 0) pred[b] = tot + outb[0];
}

__global__ void copy_k(const float* __restrict__ src, float* __restrict__ dst, int n)
{
    int i = blockIdx.x * blockDim.x + threadIdx.x;
    if (i < n) dst[i] = src[i];
}

// ---------------- launcher ----------------
extern "C" void kernel_launch(void* const* d_in, const int* in_sizes, int n_in,
                              void* d_out, int out_size)
{
    const float* atom_list    = (const float*)d_in[0];
    const float* bond_list    = (const float*)d_in[1];
    const float* atom_mask    = (const float*)d_in[2];
    const float* atom_fc_w    = (const float*)d_in[3];
    const float* atom_fc_b    = (const float*)d_in[4];
    const float* nbr_fc_w     = (const float*)d_in[5];
    const float* nbr_fc_b     = (const float*)d_in[6];
    const float* align_w      = (const float*)d_in[7];
    const float* align_b      = (const float*)d_in[8];
    const float* attend_w     = (const float*)d_in[9];
    const float* attend_b     = (const float*)d_in[10];
    const float* gru_wih      = (const float*)d_in[11];
    const float* gru_whh      = (const float*)d_in[12];
    const float* gru_bih      = (const float*)d_in[13];
    const float* gru_bhh      = (const float*)d_in[14];
    const float* mol_align_w  = (const float*)d_in[15];
    const float* mol_align_b  = (const float*)d_in[16];
    const float* mol_attend_w = (const float*)d_in[17];
    const float* mol_attend_b = (const float*)d_in[18];
    const float* mol_gru_wih  = (const float*)d_in[19];
    const float* mol_gru_whh  = (const float*)d_in[20];
    const float* mol_gru_bih  = (const float*)d_in[21];
    const float* mol_gru_bhh  = (const float*)d_in[22];
    const float* out_w        = (const float*)d_in[23];
    const float* out_b        = (const float*)d_in[24];
    const int*   adl          = (const int*)d_in[25];
    const int*   bdl          = (const int*)d_in[26];

    float *p_h, *p_act, *p_ctx, *p_P, *p_atomT, *p_bondT, *p_A64, *p_B32,
          *p_gi, *p_gh, *p_sc, *p_sn, *p_sumw, *p_Wa, *p_Wt, *p_Wb,
          *p_molf, *p_pred;
    cudaGetSymbolAddress((void**)&p_h,     g_h);
    cudaGetSymbolAddress((void**)&p_act,   g_act);
    cudaGetSymbolAddress((void**)&p_ctx,   g_ctx);
    cudaGetSymbolAddress((void**)&p_P,     g_P);
    cudaGetSymbolAddress((void**)&p_atomT, g_atomT);
    cudaGetSymbolAddress((void**)&p_bondT, g_bondT);
    cudaGetSymbolAddress((void**)&p_A64,   g_A64);
    cudaGetSymbolAddress((void**)&p_B32,   g_B32);
    cudaGetSymbolAddress((void**)&p_gi,    g_gi);
    cudaGetSymbolAddress((void**)&p_gh,    g_gh);
    cudaGetSymbolAddress((void**)&p_sc,    g_sc);
    cudaGetSymbolAddress((void**)&p_sn,    g_sn);
    cudaGetSymbolAddress((void**)&p_sumw,  g_sumw);
    cudaGetSymbolAddress((void**)&p_Wa,    g_Wa);
    cudaGetSymbolAddress((void**)&p_Wt,    g_Wt);
    cudaGetSymbolAddress((void**)&p_Wb,    g_Wb);
    cudaGetSymbolAddress((void**)&p_molf,  g_molf);
    cudaGetSymbolAddress((void**)&p_pred,  g_pred);

    float* out = (float*)d_out;
    const int HN = M_ATOM * DDIM;
    const bool direct = (out_size >= HN + BBATCH);

    // dynamic smem sizes (2 pipeline stages)
    const int SMEM_BL0 = 2 * (2 * 128 * 40 + 2 * 32 * 136) * 2;   // 75776 B
    const int SMEM_BL1 = 2 * (2 * 128 * 40 + 2 * 128 * 40) * 2;   // 81920 B
    cudaFuncSetAttribute(gemm_bf16x3_k<0,0>, cudaFuncAttributeMaxDynamicSharedMemorySize, SMEM_BL0);
    cudaFuncSetAttribute(gemm_bf16x3_k<0,1>, cudaFuncAttributeMaxDynamicSharedMemorySize, SMEM_BL0);
    cudaFuncSetAttribute(gemm_bf16x3_k<0,3>, cudaFuncAttributeMaxDynamicSharedMemorySize, SMEM_BL0);
    cudaFuncSetAttribute(gemm_bf16x3_k<1,0>, cudaFuncAttributeMaxDynamicSharedMemorySize, SMEM_BL1);

    const int gA = M_ATOM / 128;  // 256

    // ---- pad inputs / weights ----
    pad_atom_k<<<M_ATOM, 64>>>(atom_list, p_A64);
    pad_bond_k<<<M_ATOM, 32>>>(bond_list, p_B32);
    pad_w_k<<<64, 128>>>(atom_fc_w, p_Wa, FAD, 0);
    pad_w_k<<<64, 128>>>(nbr_fc_w,  p_Wt, FAD, 0);
    pad_w_k<<<32, 128>>>(nbr_fc_w,  p_Wb, FBD, FAD);

    // atom_feature -> h ; factored nbr transforms
    gemm_bf16x3_k<0,1><<<dim3(gA, 1), 256, SMEM_BL0>>>(p_A64, p_Wa, atom_fc_b, nullptr, p_h,     M_ATOM, 64, DDIM);
    gemm_bf16x3_k<0,0><<<dim3(gA, 1), 256, SMEM_BL0>>>(p_A64, p_Wt, nullptr,   nullptr, p_atomT, M_ATOM, 64, DDIM);
    gemm_bf16x3_k<0,0><<<dim3(gA, 1), 256, SMEM_BL0>>>(p_B32, p_Wb, nullptr,   nullptr, p_bondT, M_ATOM, 32, DDIM);

    // ---- radius 0 ----
    attn0_k<<<M_ATOM, 128>>>(p_h, p_atomT, p_bondT, adl, bdl, nbr_fc_b,
                             align_w, align_b, p_P, p_sumw);
    gemm_bf16x3_k<0,3><<<dim3(gA, 1), 256, SMEM_BL0>>>(p_P, attend_w, attend_b, p_sumw, p_ctx, M_ATOM, DDIM, DDIM);
    gemm_bf16x3_k<1,0><<<dim3(gA, 3), 256, SMEM_BL1>>>(p_ctx, gru_wih, nullptr, nullptr, p_gi, M_ATOM, DDIM, 384);
    gemm_bf16x3_k<1,0><<<dim3(gA, 3), 256, SMEM_BL1>>>(p_h,   gru_whh, nullptr, nullptr, p_gh, M_ATOM, DDIM, 384);
    gru_gate_k<<<(M_ATOM * DDIM + 255) / 256, 256>>>(p_gi, p_gh, gru_bih, gru_bhh, p_h, p_act, nullptr, M_ATOM);

    // ---- radii 1..R-1 ----
    for (int d = 1; d < NRAD; ++d) {
        dot2_k<<<M_ATOM, 128>>>(p_act, align_w + d * 2 * DDIM, align_w + d * 2 * DDIM + DDIM, p_sc, p_sn);
        gemm_bf16x3_k<0,0><<<dim3(gA, 1), 256, SMEM_BL0>>>(p_act, attend_w + (size_t)d * DDIM * DDIM,
                                                           nullptr, nullptr, p_P, M_ATOM, DDIM, DDIM);
        attn_k<<<M_ATOM, 128>>>(p_sc, p_sn, p_P, adl, align_b + d, attend_b + d * DDIM, p_ctx);
        gemm_bf16x3_k<1,0><<<dim3(gA, 3), 256, SMEM_BL1>>>(p_ctx, gru_wih + (size_t)d * 384 * DDIM,
                                                           nullptr, nullptr, p_gi, M_ATOM, DDIM, 384);
        gemm_bf16x3_k<1,0><<<dim3(gA, 3), 256, SMEM_BL1>>>(p_h, gru_whh + (size_t)d * 384 * DDIM,
                                                           nullptr, nullptr, p_gh, M_ATOM, DDIM, 384);
        float* oh = (direct && d == NRAD - 1) ? out : nullptr;
        gru_gate_k<<<(M_ATOM * DDIM + 255) / 256, 256>>>(p_gi, p_gh, gru_bih + d * 384,
                                                         gru_bhh + d * 384, p_h, p_act, oh, M_ATOM);
    }

    // ---- molecule phase ----
    molsum_k<<<BBATCH, 128>>>(p_act, atom_mask, p_molf);
    gemm_bf16x3_k<0,0><<<dim3(gA, 1), 256, SMEM_BL0>>>(p_act, mol_attend_w, nullptr, nullptr, p_P, M_ATOM, DDIM, DDIM);
    dot128_k<<<M_ATOM, 128>>>(p_act, mol_align_w + DDIM, p_sn);
    float* pred_dst = direct ? (out + HN) : p_pred;
    mol_k<<<BBATCH, 128>>>(p_molf, atom_mask, p_sn, p_P, mol_align_w, mol_align_b, mol_attend_b,
                           mol_gru_wih, mol_gru_whh, mol_gru_bih, mol_gru_bhh,
                           out_w, out_b, p_molf, pred_dst);

    // ---- fallback output paths ----
    if (!direct) {
        if (out_size == BBATCH) {
            copy_k<<<1, 256>>>(p_pred, out, BBATCH);
        } else {
            int n = out_size < HN ? out_size : HN;
            copy_k<<<(n + 255) / 256, 256>>>(p_h, out, n);
        }
    }
    (void)in_sizes; (void)n_in;
}

// round 8
// speedup vs baseline: 1.0038x; 1.0038x over previous
#include <cuda_runtime.h>
#include <cuda_bf16.h>
#include <mma.h>
#include <math.h>

using namespace nvcuda;

#define BBATCH 256
#define LLEN   128
#define KNBR   6
#define FAD    39
#define FBD    10
#define DDIM   128
#define NRAD   3
#define NTS    2
#define NEGV   (-9e8f)

static const int M_ATOM = BBATCH * LLEN;          // 32768

// ---------------- scratch (device globals; no allocations) ----------------
// f32 buffers
__device__ __align__(256) float g_h    [32768 * 128];
__device__ __align__(256) float g_act  [32768 * 128];
__device__ __align__(256) float g_P    [32768 * 128];
__device__ __align__(256) float g_atomT[32768 * 128];
__device__ __align__(256) float g_bondT[32768 * 128];
__device__ __align__(256) float g_gi   [32768 * 384];
__device__ __align__(256) float g_gh   [32768 * 384];
__device__ __align__(256) float g_sc   [32768];
__device__ __align__(256) float g_sn   [32768];
__device__ __align__(256) float g_sumw [32768];
__device__ __align__(256) float g_molf [256 * 128];
__device__ __align__(256) float g_pred [256];
// bf16 hi/lo activation buffers
__device__ __align__(256) __nv_bfloat16 g_A64h [32768 * 64];
__device__ __align__(256) __nv_bfloat16 g_A64l [32768 * 64];
__device__ __align__(256) __nv_bfloat16 g_B32h [32768 * 32];
__device__ __align__(256) __nv_bfloat16 g_B32l [32768 * 32];
__device__ __align__(256) __nv_bfloat16 g_hh   [32768 * 128];
__device__ __align__(256) __nv_bfloat16 g_hl   [32768 * 128];
__device__ __align__(256) __nv_bfloat16 g_acth [32768 * 128];
__device__ __align__(256) __nv_bfloat16 g_actl [32768 * 128];
__device__ __align__(256) __nv_bfloat16 g_ctxh [32768 * 128];
__device__ __align__(256) __nv_bfloat16 g_ctxl [32768 * 128];
__device__ __align__(256) __nv_bfloat16 g_Ph   [32768 * 128];
__device__ __align__(256) __nv_bfloat16 g_Pl   [32768 * 128];
// bf16 hi/lo weight buffers
__device__ __align__(256) __nv_bfloat16 g_Wah [64 * 128];
__device__ __align__(256) __nv_bfloat16 g_Wal [64 * 128];
__device__ __align__(256) __nv_bfloat16 g_Wth [64 * 128];
__device__ __align__(256) __nv_bfloat16 g_Wtl [64 * 128];
__device__ __align__(256) __nv_bfloat16 g_Wbh [32 * 128];
__device__ __align__(256) __nv_bfloat16 g_Wbl [32 * 128];
__device__ __align__(256) __nv_bfloat16 g_AWh [4 * 128 * 128];   // attend(3) + mol
__device__ __align__(256) __nv_bfloat16 g_AWl [4 * 128 * 128];
__device__ __align__(256) __nv_bfloat16 g_WIHh[3 * 384 * 128];
__device__ __align__(256) __nv_bfloat16 g_WIHl[3 * 384 * 128];
__device__ __align__(256) __nv_bfloat16 g_WHHh[3 * 384 * 128];
__device__ __align__(256) __nv_bfloat16 g_WHHl[3 * 384 * 128];

// ---------------- bf16 hi/lo split helpers ----------------
__device__ __forceinline__ void f2bf_split(float x, __nv_bfloat16& hi, __nv_bfloat16& lo)
{
    hi = __float2bfloat16(x);
    lo = __float2bfloat16(x - __bfloat162float(hi));
}
__device__ __forceinline__ void f2bf_split2(float x, float y,
                                            __nv_bfloat162& hi, __nv_bfloat162& lo)
{
    __nv_bfloat16 hx = __float2bfloat16(x);
    __nv_bfloat16 hy = __float2bfloat16(y);
    hi = __nv_bfloat162(hx, hy);
    lo = __nv_bfloat162(__float2bfloat16(x - __bfloat162float(hx)),
                        __float2bfloat16(y - __bfloat162float(hy)));
}

// =================== bf16x3 GEMM on pre-split hi/lo inputs ==================
// C = epilogue(A @ B), A given as bf16 hi/lo [M,K] row-major.
// BL=0: B hi/lo stored [K,N] row-major.  BL=1: stored [N,K] row-major (W^T).
// MODE: 0 raw, 1 lrelu(x+bias[n]), 3 elu(x + rowscale[m]*bias[n])
// OUT bit0: write f32 C;  OUT bit1: write bf16 hi/lo (Chi, Clo).
// BM=128, BN=64 (grid.y = N/64), BK=32. M%128==0, K%32==0.
template<int BL, int MODE, int OUT>
__global__ void __launch_bounds__(256) gemm_bf_k(
    const __nv_bfloat16* __restrict__ Ah, const __nv_bfloat16* __restrict__ Al,
    const __nv_bfloat16* __restrict__ Bh, const __nv_bfloat16* __restrict__ Bl,
    const float* __restrict__ bias, const float* __restrict__ rowscale,
    float* __restrict__ C, __nv_bfloat16* __restrict__ Chi, __nv_bfloat16* __restrict__ Clo,
    int M, int K, int N)
{
    constexpr int LDA = 40;
    constexpr int LDB = (BL == 0) ? 72 : 40;
    constexpr int A_SZ = 128 * LDA;                      // bf16 elems per hi/lo
    constexpr int B_SZ = (BL == 0) ? 32 * 72 : 64 * 40;
    __shared__ float buf[128 * 72];                      // 36.9 KB, aliased
    __nv_bfloat16* sAh = (__nv_bfloat16*)buf;
    __nv_bfloat16* sAl = sAh + A_SZ;
    __nv_bfloat16* sBh = sAl + A_SZ;
    __nv_bfloat16* sBl = sBh + B_SZ;

    const int tid  = threadIdx.x;
    const int warp = tid >> 5;
    const int wm = warp >> 1, wn = warp & 1;             // 4 x 2 warps of 32x32
    const int m0 = blockIdx.x * 128, n0 = blockIdx.y * 64;

    wmma::fragment<wmma::accumulator, 16, 16, 16, float> acc[2][2];
#pragma unroll
    for (int mi = 0; mi < 2; ++mi)
#pragma unroll
        for (int ni = 0; ni < 2; ++ni) wmma::fill_fragment(acc[mi][ni], 0.f);

    for (int k0 = 0; k0 < K; k0 += 32) {
        // A tiles: 128 x 32 bf16 = 512 uint4 per hi/lo
#pragma unroll
        for (int t = 0; t < 2; ++t) {
            int i = tid + t * 256;                       // [0,512)
            int row = i >> 2, q = i & 3;
            *(uint4*)(sAh + row * LDA + q * 8) =
                *(const uint4*)(Ah + (size_t)(m0 + row) * K + k0 + q * 8);
            *(uint4*)(sAl + row * LDA + q * 8) =
                *(const uint4*)(Al + (size_t)(m0 + row) * K + k0 + q * 8);
        }
        // B tiles: 2048 bf16 = 256 uint4 per hi/lo
        {
            if (BL == 0) {
                int r = tid >> 3, c = (tid & 7) * 8;     // 32 x 64
                *(uint4*)(sBh + r * LDB + c) =
                    *(const uint4*)(Bh + (size_t)(k0 + r) * N + n0 + c);
                *(uint4*)(sBl + r * LDB + c) =
                    *(const uint4*)(Bl + (size_t)(k0 + r) * N + n0 + c);
            } else {
                int r = tid >> 2, q = (tid & 3) * 8;     // 64 x 32
                *(uint4*)(sBh + r * LDB + q) =
                    *(const uint4*)(Bh + (size_t)(n0 + r) * K + k0 + q);
                *(uint4*)(sBl + r * LDB + q) =
                    *(const uint4*)(Bl + (size_t)(n0 + r) * K + k0 + q);
            }
        }
        __syncthreads();
#pragma unroll
        for (int kc = 0; kc < 32; kc += 16) {
            wmma::fragment<wmma::matrix_a, 16, 16, 16, __nv_bfloat16, wmma::row_major> ah[2], al[2];
#pragma unroll
            for (int mi = 0; mi < 2; ++mi) {
                wmma::load_matrix_sync(ah[mi], sAh + (wm * 32 + mi * 16) * LDA + kc, LDA);
                wmma::load_matrix_sync(al[mi], sAl + (wm * 32 + mi * 16) * LDA + kc, LDA);
            }
            if (BL == 0) {
                wmma::fragment<wmma::matrix_b, 16, 16, 16, __nv_bfloat16, wmma::row_major> bh[2], bl[2];
#pragma unroll
                for (int ni = 0; ni < 2; ++ni) {
                    wmma::load_matrix_sync(bh[ni], sBh + kc * LDB + wn * 32 + ni * 16, LDB);
                    wmma::load_matrix_sync(bl[ni], sBl + kc * LDB + wn * 32 + ni * 16, LDB);
                }
#pragma unroll
                for (int mi = 0; mi < 2; ++mi)
#pragma unroll
                    for (int ni = 0; ni < 2; ++ni) {
                        wmma::mma_sync(acc[mi][ni], ah[mi], bl[ni], acc[mi][ni]);
                        wmma::mma_sync(acc[mi][ni], al[mi], bh[ni], acc[mi][ni]);
                        wmma::mma_sync(acc[mi][ni], ah[mi], bh[ni], acc[mi][ni]);
                    }
            } else {
                wmma::fragment<wmma::matrix_b, 16, 16, 16, __nv_bfloat16, wmma::col_major> bh[2], bl[2];
#pragma unroll
                for (int ni = 0; ni < 2; ++ni) {
                    wmma::load_matrix_sync(bh[ni], sBh + (wn * 32 + ni * 16) * LDB + kc, LDB);
                    wmma::load_matrix_sync(bl[ni], sBl + (wn * 32 + ni * 16) * LDB + kc, LDB);
                }
#pragma unroll
                for (int mi = 0; mi < 2; ++mi)
#pragma unroll
                    for (int ni = 0; ni < 2; ++ni) {
                        wmma::mma_sync(acc[mi][ni], ah[mi], bl[ni], acc[mi][ni]);
                        wmma::mma_sync(acc[mi][ni], al[mi], bh[ni], acc[mi][ni]);
                        wmma::mma_sync(acc[mi][ni], ah[mi], bh[ni], acc[mi][ni]);
                    }
            }
        }
        __syncthreads();
    }
    // epilogue via smem staging
    float* Cs = buf;                                     // ld 72
#pragma unroll
    for (int mi = 0; mi < 2; ++mi)
#pragma unroll
        for (int ni = 0; ni < 2; ++ni)
            wmma::store_matrix_sync(Cs + (wm * 32 + mi * 16) * 72 + (wn * 32 + ni * 16),
                                    acc[mi][ni], 72, wmma::mem_row_major);
    __syncthreads();
#pragma unroll
    for (int t = 0; t < 8; ++t) {
        int i = tid + t * 256;                           // [0,2048)
        int row = i >> 4, c4 = i & 15;
        float4 v = *(float4*)(Cs + row * 72 + c4 * 4);
        int n = n0 + c4 * 4;
        if (MODE == 1) {
            v.x += bias[n];     v.y += bias[n + 1];  v.z += bias[n + 2];  v.w += bias[n + 3];
            v.x = v.x > 0.f ? v.x : 0.01f * v.x;
            v.y = v.y > 0.f ? v.y : 0.01f * v.y;
            v.z = v.z > 0.f ? v.z : 0.01f * v.z;
            v.w = v.w > 0.f ? v.w : 0.01f * v.w;
        } else if (MODE == 3) {
            float rs = rowscale[m0 + row];
            v.x += rs * bias[n];     v.y += rs * bias[n + 1];
            v.z += rs * bias[n + 2]; v.w += rs * bias[n + 3];
            v.x = v.x > 0.f ? v.x : expm1f(v.x);
            v.y = v.y > 0.f ? v.y : expm1f(v.y);
            v.z = v.z > 0.f ? v.z : expm1f(v.z);
            v.w = v.w > 0.f ? v.w : expm1f(v.w);
        }
        size_t off = (size_t)(m0 + row) * N + n;
        if (OUT & 1) *(float4*)(C + off) = v;
        if (OUT & 2) {
            __nv_bfloat162 h0, l0, h1, l1;
            f2bf_split2(v.x, v.y, h0, l0);
            f2bf_split2(v.z, v.w, h1, l1);
            *(__nv_bfloat162*)(Chi + off)     = h0;
            *(__nv_bfloat162*)(Chi + off + 2) = h1;
            *(__nv_bfloat162*)(Clo + off)     = l0;
            *(__nv_bfloat162*)(Clo + off + 2) = l1;
        }
    }
}

// ---------------- block reductions ----------------
__device__ __forceinline__ float blk_sum(float v, float* red, int j)
{
#pragma unroll
    for (int o = 16; o > 0; o >>= 1) v += __shfl_down_sync(0xffffffffu, v, o);
    if ((j & 31) == 0) red[j >> 5] = v;
    __syncthreads();
    v = red[0] + red[1] + red[2] + red[3];
    __syncthreads();
    return v;
}
__device__ __forceinline__ float blk_max(float v, float* red, int j)
{
#pragma unroll
    for (int o = 16; o > 0; o >>= 1) v = fmaxf(v, __shfl_down_sync(0xffffffffu, v, o));
    if ((j & 31) == 0) red[j >> 5] = v;
    __syncthreads();
    v = fmaxf(fmaxf(red[0], red[1]), fmaxf(red[2], red[3]));
    __syncthreads();
    return v;
}

// ---------------- padding / conversion kernels ----------------
__global__ void pad_atom_k(const float* __restrict__ atom,
                           __nv_bfloat16* __restrict__ oh, __nv_bfloat16* __restrict__ ol)
{
    int r = blockIdx.x, t = threadIdx.x;                 // 64 threads
    float v = (t < FAD) ? atom[(size_t)r * FAD + t] : 0.f;
    __nv_bfloat16 h, l; f2bf_split(v, h, l);
    oh[(size_t)r * 64 + t] = h;
    ol[(size_t)r * 64 + t] = l;
}
__global__ void pad_bond_k(const float* __restrict__ bond,
                           __nv_bfloat16* __restrict__ oh, __nv_bfloat16* __restrict__ ol)
{
    int r = blockIdx.x, t = threadIdx.x;                 // 32 threads
    float v = (t < FBD) ? bond[(size_t)r * FBD + t] : 0.f;
    __nv_bfloat16 h, l; f2bf_split(v, h, l);
    oh[(size_t)r * 32 + t] = h;
    ol[(size_t)r * 32 + t] = l;
}
__global__ void conv_pad_w_k(const float* __restrict__ w,
                             __nv_bfloat16* __restrict__ oh, __nv_bfloat16* __restrict__ ol,
                             int Ksrc, int off)
{
    int r = blockIdx.x, j = threadIdx.x;
    float v = (r < Ksrc) ? w[(off + r) * 128 + j] : 0.f;
    __nv_bfloat16 h, l; f2bf_split(v, h, l);
    oh[r * 128 + j] = h;
    ol[r * 128 + j] = l;
}
__global__ void conv_w_k(const float* __restrict__ w,
                         __nv_bfloat16* __restrict__ oh, __nv_bfloat16* __restrict__ ol, int n)
{
    int i = blockIdx.x * blockDim.x + threadIdx.x;
    if (i >= n) return;
    __nv_bfloat16 h, l; f2bf_split(w[i], h, l);
    oh[i] = h;
    ol[i] = l;
}

// ---------------- fused d=0 attention (emits hi/lo weighted sum) ----------
__global__ void attn0_k(const float* __restrict__ h, const float* __restrict__ atomT,
                        const float* __restrict__ bondT, const int* __restrict__ adl,
                        const int* __restrict__ bdl, const float* __restrict__ nbias,
                        const float* __restrict__ aw, const float* __restrict__ ab,
                        __nv_bfloat16* __restrict__ ph, __nv_bfloat16* __restrict__ pl,
                        float* __restrict__ sumw)
{
    int bl = blockIdx.x, j = threadIdx.x;                // 128 threads
    int bbase = (bl >> 7) << 7;
    __shared__ float red[4];
    const int base = bl * KNBR;
    float sc = blk_sum(h[(size_t)bl * DDIM + j] * aw[j], red, j);
    float aw2 = aw[DDIM + j];
    float ab0 = ab[0];
    float nb  = nbias[j];
    float v[KNBR], s[KNBR], msk[KNBR];
#pragma unroll
    for (int k = 0; k < KNBR; ++k) {
        int ai = adl[base + k], bi = bdl[base + k];
        float x = atomT[(size_t)(bbase + ai) * DDIM + j]
                + bondT[(size_t)(bbase + bi) * DDIM + j] + nb;
        v[k] = x > 0.f ? x : 0.01f * x;
        msk[k] = (ai == LLEN - 1) ? 0.f : 1.f;
    }
#pragma unroll
    for (int k = 0; k < KNBR; ++k) {
        float d = blk_sum(v[k] * aw2, red, j);
        float sco = sc + d + ab0;
        sco = sco > 0.f ? sco : 0.01f * sco;
        if (msk[k] == 0.f) sco += NEGV;
        s[k] = sco;
    }
    float mx = -1e30f;
#pragma unroll
    for (int k = 0; k < KNBR; ++k) mx = fmaxf(mx, s[k]);
    float ss = 0.f;
#pragma unroll
    for (int k = 0; k < KNBR; ++k) { s[k] = expf(s[k] - mx); ss += s[k]; }
    float acc = 0.f, sw = 0.f;
#pragma unroll
    for (int k = 0; k < KNBR; ++k) {
        float w = s[k] / ss * msk[k];
        acc = fmaf(w, v[k], acc);
        sw += w;
    }
    __nv_bfloat16 hh, ll; f2bf_split(acc, hh, ll);
    ph[(size_t)bl * DDIM + j] = hh;
    pl[(size_t)bl * DDIM + j] = ll;
    if (j == 0) sumw[bl] = sw;
}

// ---------------- dots ----------------
__global__ void dot2_k(const float* __restrict__ X, const float* __restrict__ w1,
                       const float* __restrict__ w2, float* __restrict__ o1,
                       float* __restrict__ o2)
{
    int row = blockIdx.x, j = threadIdx.x;
    __shared__ float red[4];
    float x = X[(size_t)row * DDIM + j];
    float a = blk_sum(x * w1[j], red, j);
    float b = blk_sum(x * w2[j], red, j);
    if (j == 0) { o1[row] = a; o2[row] = b; }
}
__global__ void dot128_k(const float* __restrict__ X, const float* __restrict__ v,
                         float* __restrict__ out)
{
    int row = blockIdx.x, j = threadIdx.x;
    __shared__ float red[4];
    float p = blk_sum(X[(size_t)row * DDIM + j] * v[j], red, j);
    if (j == 0) out[row] = p;
}

// ---------------- d>=1 attention (emits ctx hi/lo) ----------------
__global__ void attn_k(const float* __restrict__ sc, const float* __restrict__ sn,
                       const float* __restrict__ P, const int* __restrict__ adl,
                       const float* __restrict__ abp, const float* __restrict__ tb,
                       __nv_bfloat16* __restrict__ ctxh, __nv_bfloat16* __restrict__ ctxl)
{
    int bl = blockIdx.x;
    int b  = bl >> 7;
    int j  = threadIdx.x;
    __shared__ float ws[KNBR];
    __shared__ float swsh;
    __shared__ int   rowidx[KNBR];
    if (j == 0) {
        float ab = abp[0];
        float s[KNBR], msk[KNBR];
        float mx = -1e30f;
#pragma unroll
        for (int k = 0; k < KNBR; ++k) {
            int id = adl[bl * KNBR + k];
            int src = b * LLEN + id;
            rowidx[k] = src;
            float sco = sc[bl] + sn[src] + ab;
            sco = sco > 0.f ? sco : 0.01f * sco;
            bool pad = (id == LLEN - 1);
            if (pad) sco += NEGV;
            msk[k] = pad ? 0.f : 1.f;
            s[k] = sco;
            mx = fmaxf(mx, sco);
        }
        float sum = 0.f;
#pragma unroll
        for (int k = 0; k < KNBR; ++k) { s[k] = expf(s[k] - mx); sum += s[k]; }
        float sw = 0.f;
#pragma unroll
        for (int k = 0; k < KNBR; ++k) { ws[k] = s[k] / sum * msk[k]; sw += ws[k]; }
        swsh = sw;
    }
    __syncthreads();
    float c = 0.f;
#pragma unroll
    for (int k = 0; k < KNBR; ++k)
        c = fmaf(ws[k], P[(size_t)rowidx[k] * DDIM + j], c);
    c += swsh * tb[j];
    c = c > 0.f ? c : expm1f(c);
    __nv_bfloat16 hh, ll; f2bf_split(c, hh, ll);
    ctxh[(size_t)bl * DDIM + j] = hh;
    ctxl[(size_t)bl * DDIM + j] = ll;
}

// ---------------- GRU gate fusion (emits f32 + hi/lo) ----------------
__global__ void gru_gate_k(const float* __restrict__ gi, const float* __restrict__ gh,
                           const float* __restrict__ bih, const float* __restrict__ bhh,
                           float* __restrict__ h, float* __restrict__ act,
                           __nv_bfloat16* __restrict__ hh_o, __nv_bfloat16* __restrict__ hl_o,
                           __nv_bfloat16* __restrict__ ah_o, __nv_bfloat16* __restrict__ al_o,
                           float* __restrict__ out_h, int M)
{
    int idx = blockIdx.x * blockDim.x + threadIdx.x;
    if (idx >= M * DDIM) return;
    int j = idx & 127;
    size_t base = (size_t)(idx >> 7) * 384;
    float ir = gi[base + j] + bih[j];
    float iz = gi[base + 128 + j] + bih[128 + j];
    float in = gi[base + 256 + j] + bih[256 + j];
    float hr = gh[base + j] + bhh[j];
    float hz = gh[base + 128 + j] + bhh[128 + j];
    float hn = gh[base + 256 + j] + bhh[256 + j];
    float r = 1.f / (1.f + expf(-(ir + hr)));
    float z = 1.f / (1.f + expf(-(iz + hz)));
    float n = tanhf(in + r * hn);
    float hv = h[idx];
    float hnew = (1.f - z) * n + z * hv;
    float a = hnew > 0.f ? hnew : 0.f;
    h[idx] = hnew;
    act[idx] = a;
    __nv_bfloat16 bh_, bl_;
    f2bf_split(hnew, bh_, bl_);
    hh_o[idx] = bh_; hl_o[idx] = bl_;
    f2bf_split(a, bh_, bl_);
    ah_o[idx] = bh_; al_o[idx] = bl_;
    if (out_h) out_h[idx] = hnew;
}

// ---------------- masked sum over atoms ----------------
__global__ void molsum_k(const float* __restrict__ act, const float* __restrict__ mask,
                         float* __restrict__ molf)
{
    int b = blockIdx.x, j = threadIdx.x;
    float s = 0.f;
    for (int l = 0; l < LLEN; ++l)
        s = fmaf(act[((size_t)b * LLEN + l) * DDIM + j], mask[b * LLEN + l], s);
    molf[b * DDIM + j] = s;
}

// ---------------- per-molecule mol-attention + GRU ----------------
__global__ void mol_k(const float* __restrict__ molf_in, const float* __restrict__ mask,
                      const float* __restrict__ snm, const float* __restrict__ Pm,
                      const float* __restrict__ maw, const float* __restrict__ mab,
                      const float* __restrict__ matt_b,
                      const float* __restrict__ wih, const float* __restrict__ whh,
                      const float* __restrict__ bih, const float* __restrict__ bhh,
                      const float* __restrict__ outw, const float* __restrict__ outb,
                      float* __restrict__ molf_out, float* __restrict__ pred)
{
    int b = blockIdx.x;
    int j = threadIdx.x;
    __shared__ float smolf[DDIM];
    __shared__ float w[LLEN];
    __shared__ float sctx[DDIM];
    __shared__ float red[4];
    smolf[j] = molf_in[b * DDIM + j];
    float mymask = mask[b * LLEN + j];
    float mysnm  = snm[b * LLEN + j];
    float mabv   = mab[0];
    float mybias = matt_b[j];

    for (int t = 0; t < NTS; ++t) {
        __syncthreads();
        float amj = fmaxf(smolf[j], 0.f);
        float scv = blk_sum(amj * maw[j], red, j);
        float sco = scv + mysnm + mabv;
        sco = sco > 0.f ? sco : 0.01f * sco;
        if (mymask == 0.f) sco += NEGV;
        float mx = blk_max(sco, red, j);
        float ev = expf(sco - mx);
        float ss = blk_sum(ev, red, j);
        float wj = ev / ss * mymask;
        w[j] = wj;
        float sumw = blk_sum(wj, red, j);
        __syncthreads();
        float c = 0.f;
#pragma unroll 4
        for (int l = 0; l < LLEN; ++l)
            c = fmaf(w[l], Pm[((size_t)b * LLEN + l) * DDIM + j], c);
        c += sumw * mybias;
        c = c > 0.f ? c : expm1f(c);
        sctx[j] = c;
        __syncthreads();
        float gi0 = bih[j], gi1 = bih[DDIM + j], gi2 = bih[2 * DDIM + j];
        float gh0 = bhh[j], gh1 = bhh[DDIM + j], gh2 = bhh[2 * DDIM + j];
        const float* wi0 = wih + (size_t)j * DDIM;
        const float* wi1 = wih + (size_t)(DDIM + j) * DDIM;
        const float* wi2 = wih + (size_t)(2 * DDIM + j) * DDIM;
        const float* wh0 = whh + (size_t)j * DDIM;
        const float* wh1 = whh + (size_t)(DDIM + j) * DDIM;
        const float* wh2 = whh + (size_t)(2 * DDIM + j) * DDIM;
#pragma unroll 4
        for (int k = 0; k < DDIM; ++k) {
            float ck = sctx[k], hk = smolf[k];
            gi0 = fmaf(ck, wi0[k], gi0);
            gi1 = fmaf(ck, wi1[k], gi1);
            gi2 = fmaf(ck, wi2[k], gi2);
            gh0 = fmaf(hk, wh0[k], gh0);
            gh1 = fmaf(hk, wh1[k], gh1);
            gh2 = fmaf(hk, wh2[k], gh2);
        }
        float r = 1.f / (1.f + expf(-(gi0 + gh0)));
        float z = 1.f / (1.f + expf(-(gi1 + gh1)));
        float n = tanhf(gi2 + r * gh2);
        float hnew = (1.f - z) * n + z * smolf[j];
        __syncthreads();
        smolf[j] = hnew;
    }
    __syncthreads();
    molf_out[b * DDIM + j] = smolf[j];
    float tot = blk_sum(smolf[j] * outw[j], red, j);
    if (j == 0) pred[b] = tot + outb[0];
}

__global__ void copy_k(const float* __restrict__ src, float* __restrict__ dst, int n)
{
    int i = blockIdx.x * blockDim.x + threadIdx.x;
    if (i < n) dst[i] = src[i];
}

// ---------------- launcher ----------------
extern "C" void kernel_launch(void* const* d_in, const int* in_sizes, int n_in,
                              void* d_out, int out_size)
{
    const float* atom_list    = (const float*)d_in[0];
    const float* bond_list    = (const float*)d_in[1];
    const float* atom_mask    = (const float*)d_in[2];
    const float* atom_fc_w    = (const float*)d_in[3];
    const float* atom_fc_b    = (const float*)d_in[4];
    const float* nbr_fc_w     = (const float*)d_in[5];
    const float* nbr_fc_b     = (const float*)d_in[6];
    const float* align_w      = (const float*)d_in[7];
    const float* align_b      = (const float*)d_in[8];
    const float* attend_w     = (const float*)d_in[9];
    const float* attend_b     = (const float*)d_in[10];
    const float* gru_wih      = (const float*)d_in[11];
    const float* gru_whh      = (const float*)d_in[12];
    const float* gru_bih      = (const float*)d_in[13];
    const float* gru_bhh      = (const float*)d_in[14];
    const float* mol_align_w  = (const float*)d_in[15];
    const float* mol_align_b  = (const float*)d_in[16];
    const float* mol_attend_w = (const float*)d_in[17];
    const float* mol_attend_b = (const float*)d_in[18];
    const float* mol_gru_wih  = (const float*)d_in[19];
    const float* mol_gru_whh  = (const float*)d_in[20];
    const float* mol_gru_bih  = (const float*)d_in[21];
    const float* mol_gru_bhh  = (const float*)d_in[22];
    const float* out_w        = (const float*)d_in[23];
    const float* out_b        = (const float*)d_in[24];
    const int*   adl          = (const int*)d_in[25];
    const int*   bdl          = (const int*)d_in[26];

    float *p_h, *p_act, *p_P, *p_atomT, *p_bondT, *p_gi, *p_gh,
          *p_sc, *p_sn, *p_sumw, *p_molf, *p_pred;
    __nv_bfloat16 *A64h, *A64l, *B32h, *B32l, *hh, *hl, *acth, *actl,
                  *ctxh, *ctxl, *Ph, *Pl, *Wah, *Wal, *Wth, *Wtl, *Wbh, *Wbl,
                  *AWh, *AWl, *WIHh, *WIHl, *WHHh, *WHHl;
    cudaGetSymbolAddress((void**)&p_h,     g_h);
    cudaGetSymbolAddress((void**)&p_act,   g_act);
    cudaGetSymbolAddress((void**)&p_P,     g_P);
    cudaGetSymbolAddress((void**)&p_atomT, g_atomT);
    cudaGetSymbolAddress((void**)&p_bondT, g_bondT);
    cudaGetSymbolAddress((void**)&p_gi,    g_gi);
    cudaGetSymbolAddress((void**)&p_gh,    g_gh);
    cudaGetSymbolAddress((void**)&p_sc,    g_sc);
    cudaGetSymbolAddress((void**)&p_sn,    g_sn);
    cudaGetSymbolAddress((void**)&p_sumw,  g_sumw);
    cudaGetSymbolAddress((void**)&p_molf,  g_molf);
    cudaGetSymbolAddress((void**)&p_pred,  g_pred);
    cudaGetSymbolAddress((void**)&A64h, g_A64h);  cudaGetSymbolAddress((void**)&A64l, g_A64l);
    cudaGetSymbolAddress((void**)&B32h, g_B32h);  cudaGetSymbolAddress((void**)&B32l, g_B32l);
    cudaGetSymbolAddress((void**)&hh,   g_hh);    cudaGetSymbolAddress((void**)&hl,   g_hl);
    cudaGetSymbolAddress((void**)&acth, g_acth);  cudaGetSymbolAddress((void**)&actl, g_actl);
    cudaGetSymbolAddress((void**)&ctxh, g_ctxh);  cudaGetSymbolAddress((void**)&ctxl, g_ctxl);
    cudaGetSymbolAddress((void**)&Ph,   g_Ph);    cudaGetSymbolAddress((void**)&Pl,   g_Pl);
    cudaGetSymbolAddress((void**)&Wah,  g_Wah);   cudaGetSymbolAddress((void**)&Wal,  g_Wal);
    cudaGetSymbolAddress((void**)&Wth,  g_Wth);   cudaGetSymbolAddress((void**)&Wtl,  g_Wtl);
    cudaGetSymbolAddress((void**)&Wbh,  g_Wbh);   cudaGetSymbolAddress((void**)&Wbl,  g_Wbl);
    cudaGetSymbolAddress((void**)&AWh,  g_AWh);   cudaGetSymbolAddress((void**)&AWl,  g_AWl);
    cudaGetSymbolAddress((void**)&WIHh, g_WIHh);  cudaGetSymbolAddress((void**)&WIHl, g_WIHl);
    cudaGetSymbolAddress((void**)&WHHh, g_WHHh);  cudaGetSymbolAddress((void**)&WHHl, g_WHHl);

    float* out = (float*)d_out;
    const int HN = M_ATOM * DDIM;
    const bool direct = (out_size >= HN + BBATCH);
    const int gA = M_ATOM / 128;  // 256
    const int NG = M_ATOM * DDIM; // gate elements

    // ---- one-time conversions (inputs + all weights -> bf16 hi/lo) ----
    pad_atom_k<<<M_ATOM, 64>>>(atom_list, A64h, A64l);
    pad_bond_k<<<M_ATOM, 32>>>(bond_list, B32h, B32l);
    conv_pad_w_k<<<64, 128>>>(atom_fc_w, Wah, Wal, FAD, 0);
    conv_pad_w_k<<<64, 128>>>(nbr_fc_w,  Wth, Wtl, FAD, 0);
    conv_pad_w_k<<<32, 128>>>(nbr_fc_w,  Wbh, Wbl, FBD, FAD);
    conv_w_k<<<192, 256>>>(attend_w,     AWh,              AWl,              3 * 16384);
    conv_w_k<<<64,  256>>>(mol_attend_w, AWh + 3 * 16384,  AWl + 3 * 16384,  16384);
    conv_w_k<<<576, 256>>>(gru_wih, WIHh, WIHl, 3 * 49152);
    conv_w_k<<<576, 256>>>(gru_whh, WHHh, WHHl, 3 * 49152);

    // ---- entry GEMMs ----
    gemm_bf_k<0,1,3><<<dim3(gA, 2), 256>>>(A64h, A64l, Wah, Wal, atom_fc_b, nullptr,
                                           p_h, hh, hl, M_ATOM, 64, DDIM);
    gemm_bf_k<0,0,1><<<dim3(gA, 2), 256>>>(A64h, A64l, Wth, Wtl, nullptr, nullptr,
                                           p_atomT, nullptr, nullptr, M_ATOM, 64, DDIM);
    gemm_bf_k<0,0,1><<<dim3(gA, 2), 256>>>(B32h, B32l, Wbh, Wbl, nullptr, nullptr,
                                           p_bondT, nullptr, nullptr, M_ATOM, 32, DDIM);

    // ---- radius 0 ----
    attn0_k<<<M_ATOM, 128>>>(p_h, p_atomT, p_bondT, adl, bdl, nbr_fc_b,
                             align_w, align_b, Ph, Pl, p_sumw);
    gemm_bf_k<0,3,2><<<dim3(gA, 2), 256>>>(Ph, Pl, AWh, AWl, attend_b, p_sumw,
                                           nullptr, ctxh, ctxl, M_ATOM, DDIM, DDIM);
    gemm_bf_k<1,0,1><<<dim3(gA, 6), 256>>>(ctxh, ctxl, WIHh, WIHl, nullptr, nullptr,
                                           p_gi, nullptr, nullptr, M_ATOM, DDIM, 384);
    gemm_bf_k<1,0,1><<<dim3(gA, 6), 256>>>(hh, hl, WHHh, WHHl, nullptr, nullptr,
                                           p_gh, nullptr, nullptr, M_ATOM, DDIM, 384);
    gru_gate_k<<<(NG + 255) / 256, 256>>>(p_gi, p_gh, gru_bih, gru_bhh,
                                          p_h, p_act, hh, hl, acth, actl, nullptr, M_ATOM);

    // ---- radii 1..R-1 ----
    for (int d = 1; d < NRAD; ++d) {
        dot2_k<<<M_ATOM, 128>>>(p_act, align_w + d * 2 * DDIM, align_w + d * 2 * DDIM + DDIM,
                                p_sc, p_sn);
        gemm_bf_k<0,0,1><<<dim3(gA, 2), 256>>>(acth, actl, AWh + (size_t)d * 16384,
                                               AWl + (size_t)d * 16384, nullptr, nullptr,
                                               p_P, nullptr, nullptr, M_ATOM, DDIM, DDIM);
        attn_k<<<M_ATOM, 128>>>(p_sc, p_sn, p_P, adl, align_b + d, attend_b + d * DDIM,
                                ctxh, ctxl);
        gemm_bf_k<1,0,1><<<dim3(gA, 6), 256>>>(ctxh, ctxl, WIHh + (size_t)d * 49152,
                                               WIHl + (size_t)d * 49152, nullptr, nullptr,
                                               p_gi, nullptr, nullptr, M_ATOM, DDIM, 384);
        gemm_bf_k<1,0,1><<<dim3(gA, 6), 256>>>(hh, hl, WHHh + (size_t)d * 49152,
                                               WHHl + (size_t)d * 49152, nullptr, nullptr,
                                               p_gh, nullptr, nullptr, M_ATOM, DDIM, 384);
        float* oh = (direct && d == NRAD - 1) ? out : nullptr;
        gru_gate_k<<<(NG + 255) / 256, 256>>>(p_gi, p_gh, gru_bih + d * 384, gru_bhh + d * 384,
                                              p_h, p_act, hh, hl, acth, actl, oh, M_ATOM);
    }

    // ---- molecule phase ----
    molsum_k<<<BBATCH, 128>>>(p_act, atom_mask, p_molf);
    gemm_bf_k<0,0,1><<<dim3(gA, 2), 256>>>(acth, actl, AWh + 3 * 16384, AWl + 3 * 16384,
                                           nullptr, nullptr, p_P, nullptr, nullptr,
                                           M_ATOM, DDIM, DDIM);
    dot128_k<<<M_ATOM, 128>>>(p_act, mol_align_w + DDIM, p_sn);
    float* pred_dst = direct ? (out + HN) : p_pred;
    mol_k<<<BBATCH, 128>>>(p_molf, atom_mask, p_sn, p_P, mol_align_w, mol_align_b, mol_attend_b,
                           mol_gru_wih, mol_gru_whh, mol_gru_bih, mol_gru_bhh,
                           out_w, out_b, p_molf, pred_dst);

    // ---- fallback output paths ----
    if (!direct) {
        if (out_size == BBATCH) {
            copy_k<<<1, 256>>>(p_pred, out, BBATCH);
        } else {
            int n = out_size < HN ? out_size : HN;
            copy_k<<<(n + 255) / 256, 256>>>(p_h, out, n);
        }
    }
    (void)in_sizes; (void)n_in;
}

// round 9
// speedup vs baseline: 1.0773x; 1.0732x over previous
#include <cuda_runtime.h>
#include <cuda_bf16.h>
#include <mma.h>
#include <math.h>
#include <stdint.h>

using namespace nvcuda;

#define BBATCH 256
#define LLEN   128
#define KNBR   6
#define FAD    39
#define FBD    10
#define DDIM   128
#define NRAD   3
#define NTS    2
#define NEGV   (-9e8f)

static const int M_ATOM = BBATCH * LLEN;          // 32768

// ---------------- scratch (device globals; no allocations) ----------------
__device__ __align__(256) float g_h    [32768 * 128];
__device__ __align__(256) float g_act  [32768 * 128];
__device__ __align__(256) float g_P    [32768 * 128];
__device__ __align__(256) float g_atomT[32768 * 128];
__device__ __align__(256) float g_bondT[32768 * 128];
__device__ __align__(256) float g_gi   [32768 * 384];
__device__ __align__(256) float g_gh   [32768 * 384];
__device__ __align__(256) float g_sc   [32768];
__device__ __align__(256) float g_sn   [32768];
__device__ __align__(256) float g_sumw [32768];
__device__ __align__(256) float g_molf [256 * 128];
__device__ __align__(256) float g_pred [256];
// bf16 hi/lo activations
__device__ __align__(256) __nv_bfloat16 g_A64h [32768 * 64];
__device__ __align__(256) __nv_bfloat16 g_A64l [32768 * 64];
__device__ __align__(256) __nv_bfloat16 g_B32h [32768 * 32];
__device__ __align__(256) __nv_bfloat16 g_B32l [32768 * 32];
__device__ __align__(256) __nv_bfloat16 g_hh   [32768 * 128];
__device__ __align__(256) __nv_bfloat16 g_hl   [32768 * 128];
__device__ __align__(256) __nv_bfloat16 g_acth [32768 * 128];
__device__ __align__(256) __nv_bfloat16 g_actl [32768 * 128];
__device__ __align__(256) __nv_bfloat16 g_ctxh [32768 * 128];
__device__ __align__(256) __nv_bfloat16 g_ctxl [32768 * 128];
__device__ __align__(256) __nv_bfloat16 g_Ph   [32768 * 128];
__device__ __align__(256) __nv_bfloat16 g_Pl   [32768 * 128];
// bf16 hi/lo weights
__device__ __align__(256) __nv_bfloat16 g_Wah [64 * 128];
__device__ __align__(256) __nv_bfloat16 g_Wal [64 * 128];
__device__ __align__(256) __nv_bfloat16 g_Wth [64 * 128];
__device__ __align__(256) __nv_bfloat16 g_Wtl [64 * 128];
__device__ __align__(256) __nv_bfloat16 g_Wbh [32 * 128];
__device__ __align__(256) __nv_bfloat16 g_Wbl [32 * 128];
__device__ __align__(256) __nv_bfloat16 g_AWh [4 * 128 * 128];
__device__ __align__(256) __nv_bfloat16 g_AWl [4 * 128 * 128];
__device__ __align__(256) __nv_bfloat16 g_WIHh[3 * 384 * 128];
__device__ __align__(256) __nv_bfloat16 g_WIHl[3 * 384 * 128];
__device__ __align__(256) __nv_bfloat16 g_WHHh[3 * 384 * 128];
__device__ __align__(256) __nv_bfloat16 g_WHHl[3 * 384 * 128];

// ---------------- helpers ----------------
__device__ __forceinline__ void f2bf_split(float x, __nv_bfloat16& hi, __nv_bfloat16& lo)
{
    hi = __float2bfloat16(x);
    lo = __float2bfloat16(x - __bfloat162float(hi));
}
__device__ __forceinline__ void f2bf_split2(float x, float y,
                                            __nv_bfloat162& hi, __nv_bfloat162& lo)
{
    __nv_bfloat16 hx = __float2bfloat16(x);
    __nv_bfloat16 hy = __float2bfloat16(y);
    hi = __nv_bfloat162(hx, hy);
    lo = __nv_bfloat162(__float2bfloat16(x - __bfloat162float(hx)),
                        __float2bfloat16(y - __bfloat162float(hy)));
}
__device__ __forceinline__ uint32_t smem_u32(const void* p)
{
    uint32_t a;
    asm("{ .reg .u64 t; cvta.to.shared.u64 t, %1; cvt.u32.u64 %0, t; }" : "=r"(a) : "l"(p));
    return a;
}
__device__ __forceinline__ void cp16(uint32_t dst, const void* src)
{
    asm volatile("cp.async.ca.shared.global [%0], [%1], 16;" :: "r"(dst), "l"(src));
}
__device__ __forceinline__ void cp_commit() { asm volatile("cp.async.commit_group;"); }
__device__ __forceinline__ void cp_wait1()  { asm volatile("cp.async.wait_group 1;"); }
__device__ __forceinline__ void cp_wait0()  { asm volatile("cp.async.wait_group 0;"); }

// ============== bf16x3 GEMM body, cp.async 2-stage pipeline ================
// A hi/lo [M,K] row-major. BL=0: B hi/lo [K,N] row-major; BL=1: [N,K] (W^T).
// MODE: 0 raw, 1 lrelu(x+bias), 3 elu(x + rowscale*bias)
// OUT bit0 f32 C; bit1 bf16 hi/lo Chi/Clo. BM=128, BN=64, BK=32.
template<int BL, int MODE, int OUT>
__device__ __forceinline__ void gemm_body(
    const __nv_bfloat16* __restrict__ Ah, const __nv_bfloat16* __restrict__ Al,
    const __nv_bfloat16* __restrict__ Bh, const __nv_bfloat16* __restrict__ Bl,
    const float* __restrict__ bias, const float* __restrict__ rowscale,
    float* __restrict__ C, __nv_bfloat16* __restrict__ Chi, __nv_bfloat16* __restrict__ Clo,
    int K, int N, char* dyn)
{
    constexpr int LDA = 40;
    constexpr int LDB = (BL == 0) ? 72 : 40;
    constexpr int A_SZ = 128 * LDA;                       // bf16 elems per buf
    constexpr int B_SZ = (BL == 0) ? 32 * 72 : 64 * 40;
    constexpr int STG  = 2 * A_SZ + 2 * B_SZ;             // bf16 elems per stage

    __nv_bfloat16* base = (__nv_bfloat16*)dyn;
    const uint32_t sbase = smem_u32(dyn);
    const int tid  = threadIdx.x;
    const int warp = tid >> 5;
    const int wm = warp >> 1, wn = warp & 1;
    const int m0 = blockIdx.x * 128, n0 = blockIdx.y * 64;

    auto issue = [&](int kt, int s) {
        const int k0 = kt << 5;
        const uint32_t su = sbase + (uint32_t)s * STG * 2;
#pragma unroll
        for (int t = 0; t < 2; ++t) {
            int i = tid + t * 256;                        // [0,512)
            int row = i >> 2, q = (i & 3) * 8;
            size_t goff = (size_t)(m0 + row) * K + k0 + q;
            cp16(su + (row * LDA + q) * 2,          Ah + goff);
            cp16(su + (A_SZ + row * LDA + q) * 2,   Al + goff);
        }
        if (BL == 0) {
            int r = tid >> 3, c = (tid & 7) * 8;          // 32 x 64
            size_t goff = (size_t)(k0 + r) * N + n0 + c;
            cp16(su + (2 * A_SZ + r * LDB + c) * 2,        Bh + goff);
            cp16(su + (2 * A_SZ + B_SZ + r * LDB + c) * 2, Bl + goff);
        } else {
            int r = tid >> 2, q = (tid & 3) * 8;          // 64 x 32
            size_t goff = (size_t)(n0 + r) * K + k0 + q;
            cp16(su + (2 * A_SZ + r * LDB + q) * 2,        Bh + goff);
            cp16(su + (2 * A_SZ + B_SZ + r * LDB + q) * 2, Bl + goff);
        }
        cp_commit();
    };

    wmma::fragment<wmma::accumulator, 16, 16, 16, float> acc[2][2];
#pragma unroll
    for (int mi = 0; mi < 2; ++mi)
#pragma unroll
        for (int ni = 0; ni < 2; ++ni) wmma::fill_fragment(acc[mi][ni], 0.f);

    const int nk = K >> 5;
    issue(0, 0);
    for (int kt = 0; kt < nk; ++kt) {
        if (kt + 1 < nk) { issue(kt + 1, (kt + 1) & 1); cp_wait1(); }
        else             { cp_wait0(); }
        __syncthreads();
        const __nv_bfloat16* st  = base + (size_t)(kt & 1) * STG;
        const __nv_bfloat16* sAh = st;
        const __nv_bfloat16* sAl = st + A_SZ;
        const __nv_bfloat16* sBh = st + 2 * A_SZ;
        const __nv_bfloat16* sBl = sBh + B_SZ;
#pragma unroll
        for (int kc = 0; kc < 32; kc += 16) {
            wmma::fragment<wmma::matrix_a, 16, 16, 16, __nv_bfloat16, wmma::row_major> ah[2], al[2];
#pragma unroll
            for (int mi = 0; mi < 2; ++mi) {
                wmma::load_matrix_sync(ah[mi], sAh + (wm * 32 + mi * 16) * LDA + kc, LDA);
                wmma::load_matrix_sync(al[mi], sAl + (wm * 32 + mi * 16) * LDA + kc, LDA);
            }
            if (BL == 0) {
                wmma::fragment<wmma::matrix_b, 16, 16, 16, __nv_bfloat16, wmma::row_major> bh[2], bl[2];
#pragma unroll
                for (int ni = 0; ni < 2; ++ni) {
                    wmma::load_matrix_sync(bh[ni], sBh + kc * LDB + wn * 32 + ni * 16, LDB);
                    wmma::load_matrix_sync(bl[ni], sBl + kc * LDB + wn * 32 + ni * 16, LDB);
                }
#pragma unroll
                for (int mi = 0; mi < 2; ++mi)
#pragma unroll
                    for (int ni = 0; ni < 2; ++ni) {
                        wmma::mma_sync(acc[mi][ni], ah[mi], bl[ni], acc[mi][ni]);
                        wmma::mma_sync(acc[mi][ni], al[mi], bh[ni], acc[mi][ni]);
                        wmma::mma_sync(acc[mi][ni], ah[mi], bh[ni], acc[mi][ni]);
                    }
            } else {
                wmma::fragment<wmma::matrix_b, 16, 16, 16, __nv_bfloat16, wmma::col_major> bh[2], bl[2];
#pragma unroll
                for (int ni = 0; ni < 2; ++ni) {
                    wmma::load_matrix_sync(bh[ni], sBh + (wn * 32 + ni * 16) * LDB + kc, LDB);
                    wmma::load_matrix_sync(bl[ni], sBl + (wn * 32 + ni * 16) * LDB + kc, LDB);
                }
#pragma unroll
                for (int mi = 0; mi < 2; ++mi)
#pragma unroll
                    for (int ni = 0; ni < 2; ++ni) {
                        wmma::mma_sync(acc[mi][ni], ah[mi], bl[ni], acc[mi][ni]);
                        wmma::mma_sync(acc[mi][ni], al[mi], bh[ni], acc[mi][ni]);
                        wmma::mma_sync(acc[mi][ni], ah[mi], bh[ni], acc[mi][ni]);
                    }
            }
        }
        __syncthreads();
    }
    // epilogue (reuse dyn as f32 staging)
    float* Cs = (float*)dyn;                              // ld 72
#pragma unroll
    for (int mi = 0; mi < 2; ++mi)
#pragma unroll
        for (int ni = 0; ni < 2; ++ni)
            wmma::store_matrix_sync(Cs + (wm * 32 + mi * 16) * 72 + (wn * 32 + ni * 16),
                                    acc[mi][ni], 72, wmma::mem_row_major);
    __syncthreads();
#pragma unroll
    for (int t = 0; t < 8; ++t) {
        int i = tid + t * 256;
        int row = i >> 4, c4 = i & 15;
        float4 v = *(float4*)(Cs + row * 72 + c4 * 4);
        int n = n0 + c4 * 4;
        if (MODE == 1) {
            v.x += bias[n];     v.y += bias[n + 1];  v.z += bias[n + 2];  v.w += bias[n + 3];
            v.x = v.x > 0.f ? v.x : 0.01f * v.x;
            v.y = v.y > 0.f ? v.y : 0.01f * v.y;
            v.z = v.z > 0.f ? v.z : 0.01f * v.z;
            v.w = v.w > 0.f ? v.w : 0.01f * v.w;
        } else if (MODE == 3) {
            float rs = rowscale[m0 + row];
            v.x += rs * bias[n];     v.y += rs * bias[n + 1];
            v.z += rs * bias[n + 2]; v.w += rs * bias[n + 3];
            v.x = v.x > 0.f ? v.x : expm1f(v.x);
            v.y = v.y > 0.f ? v.y : expm1f(v.y);
            v.z = v.z > 0.f ? v.z : expm1f(v.z);
            v.w = v.w > 0.f ? v.w : expm1f(v.w);
        }
        size_t off = (size_t)(m0 + row) * N + n;
        if (OUT & 1) *(float4*)(C + off) = v;
        if (OUT & 2) {
            __nv_bfloat162 h0, l0, h1, l1;
            f2bf_split2(v.x, v.y, h0, l0);
            f2bf_split2(v.z, v.w, h1, l1);
            *(__nv_bfloat162*)(Chi + off)     = h0;
            *(__nv_bfloat162*)(Chi + off + 2) = h1;
            *(__nv_bfloat162*)(Clo + off)     = l0;
            *(__nv_bfloat162*)(Clo + off + 2) = l1;
        }
    }
}

template<int BL, int MODE, int OUT>
__global__ void __launch_bounds__(256) gemm_bf_k(
    const __nv_bfloat16* __restrict__ Ah, const __nv_bfloat16* __restrict__ Al,
    const __nv_bfloat16* __restrict__ Bh, const __nv_bfloat16* __restrict__ Bl,
    const float* __restrict__ bias, const float* __restrict__ rowscale,
    float* __restrict__ C, __nv_bfloat16* __restrict__ Chi, __nv_bfloat16* __restrict__ Clo,
    int K, int N)
{
    extern __shared__ __align__(16) char dyn[];
    gemm_body<BL, MODE, OUT>(Ah, Al, Bh, Bl, bias, rowscale, C, Chi, Clo, K, N, dyn);
}

// merged GRU GEMM: z=0 -> gi = ctx@WIH^T, z=1 -> gh = h@WHH^T
__global__ void __launch_bounds__(256) gemm_gru_k(
    const __nv_bfloat16* __restrict__ ctxh, const __nv_bfloat16* __restrict__ ctxl,
    const __nv_bfloat16* __restrict__ hh,   const __nv_bfloat16* __restrict__ hl,
    const __nv_bfloat16* __restrict__ WIHh, const __nv_bfloat16* __restrict__ WIHl,
    const __nv_bfloat16* __restrict__ WHHh, const __nv_bfloat16* __restrict__ WHHl,
    float* __restrict__ gi, float* __restrict__ gh)
{
    extern __shared__ __align__(16) char dyn[];
    if (blockIdx.z == 0)
        gemm_body<1, 0, 1>(ctxh, ctxl, WIHh, WIHl, nullptr, nullptr,
                           gi, nullptr, nullptr, DDIM, 384, dyn);
    else
        gemm_body<1, 0, 1>(hh, hl, WHHh, WHHl, nullptr, nullptr,
                           gh, nullptr, nullptr, DDIM, 384, dyn);
}

// ---------------- block reductions ----------------
__device__ __forceinline__ float blk_sum(float v, float* red, int j)
{
#pragma unroll
    for (int o = 16; o > 0; o >>= 1) v += __shfl_down_sync(0xffffffffu, v, o);
    if ((j & 31) == 0) red[j >> 5] = v;
    __syncthreads();
    v = red[0] + red[1] + red[2] + red[3];
    __syncthreads();
    return v;
}
__device__ __forceinline__ float blk_max(float v, float* red, int j)
{
#pragma unroll
    for (int o = 16; o > 0; o >>= 1) v = fmaxf(v, __shfl_down_sync(0xffffffffu, v, o));
    if ((j & 31) == 0) red[j >> 5] = v;
    __syncthreads();
    v = fmaxf(fmaxf(red[0], red[1]), fmaxf(red[2], red[3]));
    __syncthreads();
    return v;
}

// ---------------- padding / conversion kernels ----------------
__global__ void pad_atom_k(const float* __restrict__ atom,
                           __nv_bfloat16* __restrict__ oh, __nv_bfloat16* __restrict__ ol)
{
    int r = blockIdx.x, t = threadIdx.x;
    float v = (t < FAD) ? atom[(size_t)r * FAD + t] : 0.f;
    __nv_bfloat16 h, l; f2bf_split(v, h, l);
    oh[(size_t)r * 64 + t] = h;
    ol[(size_t)r * 64 + t] = l;
}
__global__ void pad_bond_k(const float* __restrict__ bond,
                           __nv_bfloat16* __restrict__ oh, __nv_bfloat16* __restrict__ ol)
{
    int r = blockIdx.x, t = threadIdx.x;
    float v = (t < FBD) ? bond[(size_t)r * FBD + t] : 0.f;
    __nv_bfloat16 h, l; f2bf_split(v, h, l);
    oh[(size_t)r * 32 + t] = h;
    ol[(size_t)r * 32 + t] = l;
}
__global__ void conv_pad_w_k(const float* __restrict__ w,
                             __nv_bfloat16* __restrict__ oh, __nv_bfloat16* __restrict__ ol,
                             int Ksrc, int off)
{
    int r = blockIdx.x, j = threadIdx.x;
    float v = (r < Ksrc) ? w[(off + r) * 128 + j] : 0.f;
    __nv_bfloat16 h, l; f2bf_split(v, h, l);
    oh[r * 128 + j] = h;
    ol[r * 128 + j] = l;
}
__global__ void conv_w_k(const float* __restrict__ w,
                         __nv_bfloat16* __restrict__ oh, __nv_bfloat16* __restrict__ ol, int n)
{
    int i = blockIdx.x * blockDim.x + threadIdx.x;
    if (i >= n) return;
    __nv_bfloat16 h, l; f2bf_split(w[i], h, l);
    oh[i] = h;
    ol[i] = l;
}

// ---------------- fused d=0 attention ----------------
__global__ void attn0_k(const float* __restrict__ h, const float* __restrict__ atomT,
                        const float* __restrict__ bondT, const int* __restrict__ adl,
                        const int* __restrict__ bdl, const float* __restrict__ nbias,
                        const float* __restrict__ aw, const float* __restrict__ ab,
                        __nv_bfloat16* __restrict__ ph, __nv_bfloat16* __restrict__ pl,
                        float* __restrict__ sumw)
{
    int bl = blockIdx.x, j = threadIdx.x;
    int bbase = (bl >> 7) << 7;
    __shared__ float red[4];
    const int base = bl * KNBR;
    float sc = blk_sum(h[(size_t)bl * DDIM + j] * aw[j], red, j);
    float aw2 = aw[DDIM + j];
    float ab0 = ab[0];
    float nb  = nbias[j];
    float v[KNBR], s[KNBR], msk[KNBR];
#pragma unroll
    for (int k = 0; k < KNBR; ++k) {
        int ai = adl[base + k], bi = bdl[base + k];
        float x = atomT[(size_t)(bbase + ai) * DDIM + j]
                + bondT[(size_t)(bbase + bi) * DDIM + j] + nb;
        v[k] = x > 0.f ? x : 0.01f * x;
        msk[k] = (ai == LLEN - 1) ? 0.f : 1.f;
    }
#pragma unroll
    for (int k = 0; k < KNBR; ++k) {
        float d = blk_sum(v[k] * aw2, red, j);
        float sco = sc + d + ab0;
        sco = sco > 0.f ? sco : 0.01f * sco;
        if (msk[k] == 0.f) sco += NEGV;
        s[k] = sco;
    }
    float mx = -1e30f;
#pragma unroll
    for (int k = 0; k < KNBR; ++k) mx = fmaxf(mx, s[k]);
    float ss = 0.f;
#pragma unroll
    for (int k = 0; k < KNBR; ++k) { s[k] = expf(s[k] - mx); ss += s[k]; }
    float acc = 0.f, sw = 0.f;
#pragma unroll
    for (int k = 0; k < KNBR; ++k) {
        float w = s[k] / ss * msk[k];
        acc = fmaf(w, v[k], acc);
        sw += w;
    }
    __nv_bfloat16 hh_, ll_; f2bf_split(acc, hh_, ll_);
    ph[(size_t)bl * DDIM + j] = hh_;
    pl[(size_t)bl * DDIM + j] = ll_;
    if (j == 0) sumw[bl] = sw;
}

// ---------------- dots ----------------
__global__ void dot2_k(const float* __restrict__ X, const float* __restrict__ w1,
                       const float* __restrict__ w2, float* __restrict__ o1,
                       float* __restrict__ o2)
{
    int row = blockIdx.x, j = threadIdx.x;
    __shared__ float red[4];
    float x = X[(size_t)row * DDIM + j];
    float a = blk_sum(x * w1[j], red, j);
    float b = blk_sum(x * w2[j], red, j);
    if (j == 0) { o1[row] = a; o2[row] = b; }
}
__global__ void dot128_k(const float* __restrict__ X, const float* __restrict__ v,
                         float* __restrict__ out)
{
    int row = blockIdx.x, j = threadIdx.x;
    __shared__ float red[4];
    float p = blk_sum(X[(size_t)row * DDIM + j] * v[j], red, j);
    if (j == 0) out[row] = p;
}

// ---------------- d>=1 attention ----------------
__global__ void attn_k(const float* __restrict__ sc, const float* __restrict__ sn,
                       const float* __restrict__ P, const int* __restrict__ adl,
                       const float* __restrict__ abp, const float* __restrict__ tb,
                       __nv_bfloat16* __restrict__ ctxh, __nv_bfloat16* __restrict__ ctxl)
{
    int bl = blockIdx.x;
    int b  = bl >> 7;
    int j  = threadIdx.x;
    __shared__ float ws[KNBR];
    __shared__ float swsh;
    __shared__ int   rowidx[KNBR];
    if (j == 0) {
        float ab = abp[0];
        float s[KNBR], msk[KNBR];
        float mx = -1e30f;
#pragma unroll
        for (int k = 0; k < KNBR; ++k) {
            int id = adl[bl * KNBR + k];
            int src = b * LLEN + id;
            rowidx[k] = src;
            float sco = sc[bl] + sn[src] + ab;
            sco = sco > 0.f ? sco : 0.01f * sco;
            bool pad = (id == LLEN - 1);
            if (pad) sco += NEGV;
            msk[k] = pad ? 0.f : 1.f;
            s[k] = sco;
            mx = fmaxf(mx, sco);
        }
        float sum = 0.f;
#pragma unroll
        for (int k = 0; k < KNBR; ++k) { s[k] = expf(s[k] - mx); sum += s[k]; }
        float sw = 0.f;
#pragma unroll
        for (int k = 0; k < KNBR; ++k) { ws[k] = s[k] / sum * msk[k]; sw += ws[k]; }
        swsh = sw;
    }
    __syncthreads();
    float c = 0.f;
#pragma unroll
    for (int k = 0; k < KNBR; ++k)
        c = fmaf(ws[k], P[(size_t)rowidx[k] * DDIM + j], c);
    c += swsh * tb[j];
    c = c > 0.f ? c : expm1f(c);
    __nv_bfloat16 hh_, ll_; f2bf_split(c, hh_, ll_);
    ctxh[(size_t)bl * DDIM + j] = hh_;
    ctxl[(size_t)bl * DDIM + j] = ll_;
}

// ---------------- GRU gate fusion, float4-vectorized ----------------
__global__ void gru_gate_k(const float* __restrict__ gi, const float* __restrict__ gh,
                           const float* __restrict__ bih, const float* __restrict__ bhh,
                           float* __restrict__ h, float* __restrict__ act,
                           __nv_bfloat16* __restrict__ hh_o, __nv_bfloat16* __restrict__ hl_o,
                           __nv_bfloat16* __restrict__ ah_o, __nv_bfloat16* __restrict__ al_o,
                           float* __restrict__ out_h, int M)
{
    int g4 = blockIdx.x * blockDim.x + threadIdx.x;      // group of 4 elems
    if (g4 >= M * 32) return;
    int m = g4 >> 5, j = (g4 & 31) * 4;
    size_t gbase = (size_t)m * 384 + j;
    size_t hbase = (size_t)m * 128 + j;
    float4 ir = *(const float4*)(gi + gbase);
    float4 iz = *(const float4*)(gi + gbase + 128);
    float4 in = *(const float4*)(gi + gbase + 256);
    float4 hr = *(const float4*)(gh + gbase);
    float4 hz = *(const float4*)(gh + gbase + 128);
    float4 hn = *(const float4*)(gh + gbase + 256);
    float4 b0 = *(const float4*)(bih + j);
    float4 b1 = *(const float4*)(bih + 128 + j);
    float4 b2 = *(const float4*)(bih + 256 + j);
    float4 c0 = *(const float4*)(bhh + j);
    float4 c1 = *(const float4*)(bhh + 128 + j);
    float4 c2 = *(const float4*)(bhh + 256 + j);
    float4 hv = *(const float4*)(h + hbase);
    float4 hnew, av;
#pragma unroll
    for (int e = 0; e < 4; ++e) {
        float irv = (&ir.x)[e] + (&b0.x)[e];
        float izv = (&iz.x)[e] + (&b1.x)[e];
        float inv = (&in.x)[e] + (&b2.x)[e];
        float hrv = (&hr.x)[e] + (&c0.x)[e];
        float hzv = (&hz.x)[e] + (&c1.x)[e];
        float hnv = (&hn.x)[e] + (&c2.x)[e];
        float r = 1.f / (1.f + expf(-(irv + hrv)));
        float z = 1.f / (1.f + expf(-(izv + hzv)));
        float n = tanhf(inv + r * hnv);
        float ho = (1.f - z) * n + z * (&hv.x)[e];
        (&hnew.x)[e] = ho;
        (&av.x)[e] = ho > 0.f ? ho : 0.f;
    }
    *(float4*)(h + hbase)   = hnew;
    *(float4*)(act + hbase) = av;
    __nv_bfloat162 h0, l0, h1, l1;
    f2bf_split2(hnew.x, hnew.y, h0, l0);
    f2bf_split2(hnew.z, hnew.w, h1, l1);
    *(__nv_bfloat162*)(hh_o + hbase)     = h0;
    *(__nv_bfloat162*)(hh_o + hbase + 2) = h1;
    *(__nv_bfloat162*)(hl_o + hbase)     = l0;
    *(__nv_bfloat162*)(hl_o + hbase + 2) = l1;
    f2bf_split2(av.x, av.y, h0, l0);
    f2bf_split2(av.z, av.w, h1, l1);
    *(__nv_bfloat162*)(ah_o + hbase)     = h0;
    *(__nv_bfloat162*)(ah_o + hbase + 2) = h1;
    *(__nv_bfloat162*)(al_o + hbase)     = l0;
    *(__nv_bfloat162*)(al_o + hbase + 2) = l1;
    if (out_h) *(float4*)(out_h + hbase) = hnew;
}

// ---------------- masked sum over atoms ----------------
__global__ void molsum_k(const float* __restrict__ act, const float* __restrict__ mask,
                         float* __restrict__ molf)
{
    int b = blockIdx.x, j = threadIdx.x;
    float s = 0.f;
    for (int l = 0; l < LLEN; ++l)
        s = fmaf(act[((size_t)b * LLEN + l) * DDIM + j], mask[b * LLEN + l], s);
    molf[b * DDIM + j] = s;
}

// ---------------- per-molecule mol-attention + GRU ----------------
__global__ void mol_k(const float* __restrict__ molf_in, const float* __restrict__ mask,
                      const float* __restrict__ snm, const float* __restrict__ Pm,
                      const float* __restrict__ maw, const float* __restrict__ mab,
                      const float* __restrict__ matt_b,
                      const float* __restrict__ wih, const float* __restrict__ whh,
                      const float* __restrict__ bih, const float* __restrict__ bhh,
                      const float* __restrict__ outw, const float* __restrict__ outb,
                      float* __restrict__ molf_out, float* __restrict__ pred)
{
    int b = blockIdx.x;
    int j = threadIdx.x;
    __shared__ float smolf[DDIM];
    __shared__ float w[LLEN];
    __shared__ float sctx[DDIM];
    __shared__ float red[4];
    smolf[j] = molf_in[b * DDIM + j];
    float mymask = mask[b * LLEN + j];
    float mysnm  = snm[b * LLEN + j];
    float mabv   = mab[0];
    float mybias = matt_b[j];

    for (int t = 0; t < NTS; ++t) {
        __syncthreads();
        float amj = fmaxf(smolf[j], 0.f);
        float scv = blk_sum(amj * maw[j], red, j);
        float sco = scv + mysnm + mabv;
        sco = sco > 0.f ? sco : 0.01f * sco;
        if (mymask == 0.f) sco += NEGV;
        float mx = blk_max(sco, red, j);
        float ev = expf(sco - mx);
        float ss = blk_sum(ev, red, j);
        float wj = ev / ss * mymask;
        w[j] = wj;
        float sumw = blk_sum(wj, red, j);
        __syncthreads();
        float c = 0.f;
#pragma unroll 4
        for (int l = 0; l < LLEN; ++l)
            c = fmaf(w[l], Pm[((size_t)b * LLEN + l) * DDIM + j], c);
        c += sumw * mybias;
        c = c > 0.f ? c : expm1f(c);
        sctx[j] = c;
        __syncthreads();
        float gi0 = bih[j], gi1 = bih[DDIM + j], gi2 = bih[2 * DDIM + j];
        float gh0 = bhh[j], gh1 = bhh[DDIM + j], gh2 = bhh[2 * DDIM + j];
        const float* wi0 = wih + (size_t)j * DDIM;
        const float* wi1 = wih + (size_t)(DDIM + j) * DDIM;
        const float* wi2 = wih + (size_t)(2 * DDIM + j) * DDIM;
        const float* wh0 = whh + (size_t)j * DDIM;
        const float* wh1 = whh + (size_t)(DDIM + j) * DDIM;
        const float* wh2 = whh + (size_t)(2 * DDIM + j) * DDIM;
#pragma unroll 4
        for (int k = 0; k < DDIM; ++k) {
            float ck = sctx[k], hk = smolf[k];
            gi0 = fmaf(ck, wi0[k], gi0);
            gi1 = fmaf(ck, wi1[k], gi1);
            gi2 = fmaf(ck, wi2[k], gi2);
            gh0 = fmaf(hk, wh0[k], gh0);
            gh1 = fmaf(hk, wh1[k], gh1);
            gh2 = fmaf(hk, wh2[k], gh2);
        }
        float r = 1.f / (1.f + expf(-(gi0 + gh0)));
        float z = 1.f / (1.f + expf(-(gi1 + gh1)));
        float n = tanhf(gi2 + r * gh2);
        float hnew = (1.f - z) * n + z * smolf[j];
        __syncthreads();
        smolf[j] = hnew;
    }
    __syncthreads();
    molf_out[b * DDIM + j] = smolf[j];
    float tot = blk_sum(smolf[j] * outw[j], red, j);
    if (j == 0) pred[b] = tot + outb[0];
}

__global__ void copy_k(const float* __restrict__ src, float* __restrict__ dst, int n)
{
    int i = blockIdx.x * blockDim.x + threadIdx.x;
    if (i < n) dst[i] = src[i];
}

// ---------------- launcher ----------------
extern "C" void kernel_launch(void* const* d_in, const int* in_sizes, int n_in,
                              void* d_out, int out_size)
{
    const float* atom_list    = (const float*)d_in[0];
    const float* bond_list    = (const float*)d_in[1];
    const float* atom_mask    = (const float*)d_in[2];
    const float* atom_fc_w    = (const float*)d_in[3];
    const float* atom_fc_b    = (const float*)d_in[4];
    const float* nbr_fc_w     = (const float*)d_in[5];
    const float* nbr_fc_b     = (const float*)d_in[6];
    const float* align_w      = (const float*)d_in[7];
    const float* align_b      = (const float*)d_in[8];
    const float* attend_w     = (const float*)d_in[9];
    const float* attend_b     = (const float*)d_in[10];
    const float* gru_wih      = (const float*)d_in[11];
    const float* gru_whh      = (const float*)d_in[12];
    const float* gru_bih      = (const float*)d_in[13];
    const float* gru_bhh      = (const float*)d_in[14];
    const float* mol_align_w  = (const float*)d_in[15];
    const float* mol_align_b  = (const float*)d_in[16];
    const float* mol_attend_w = (const float*)d_in[17];
    const float* mol_attend_b = (const float*)d_in[18];
    const float* mol_gru_wih  = (const float*)d_in[19];
    const float* mol_gru_whh  = (const float*)d_in[20];
    const float* mol_gru_bih  = (const float*)d_in[21];
    const float* mol_gru_bhh  = (const float*)d_in[22];
    const float* out_w        = (const float*)d_in[23];
    const float* out_b        = (const float*)d_in[24];
    const int*   adl          = (const int*)d_in[25];
    const int*   bdl          = (const int*)d_in[26];

    float *p_h, *p_act, *p_P, *p_atomT, *p_bondT, *p_gi, *p_gh,
          *p_sc, *p_sn, *p_sumw, *p_molf, *p_pred;
    __nv_bfloat16 *A64h, *A64l, *B32h, *B32l, *hh, *hl, *acth, *actl,
                  *ctxh, *ctxl, *Ph, *Pl, *Wah, *Wal, *Wth, *Wtl, *Wbh, *Wbl,
                  *AWh, *AWl, *WIHh, *WIHl, *WHHh, *WHHl;
    cudaGetSymbolAddress((void**)&p_h,     g_h);
    cudaGetSymbolAddress((void**)&p_act,   g_act);
    cudaGetSymbolAddress((void**)&p_P,     g_P);
    cudaGetSymbolAddress((void**)&p_atomT, g_atomT);
    cudaGetSymbolAddress((void**)&p_bondT, g_bondT);
    cudaGetSymbolAddress((void**)&p_gi,    g_gi);
    cudaGetSymbolAddress((void**)&p_gh,    g_gh);
    cudaGetSymbolAddress((void**)&p_sc,    g_sc);
    cudaGetSymbolAddress((void**)&p_sn,    g_sn);
    cudaGetSymbolAddress((void**)&p_sumw,  g_sumw);
    cudaGetSymbolAddress((void**)&p_molf,  g_molf);
    cudaGetSymbolAddress((void**)&p_pred,  g_pred);
    cudaGetSymbolAddress((void**)&A64h, g_A64h);  cudaGetSymbolAddress((void**)&A64l, g_A64l);
    cudaGetSymbolAddress((void**)&B32h, g_B32h);  cudaGetSymbolAddress((void**)&B32l, g_B32l);
    cudaGetSymbolAddress((void**)&hh,   g_hh);    cudaGetSymbolAddress((void**)&hl,   g_hl);
    cudaGetSymbolAddress((void**)&acth, g_acth);  cudaGetSymbolAddress((void**)&actl, g_actl);
    cudaGetSymbolAddress((void**)&ctxh, g_ctxh);  cudaGetSymbolAddress((void**)&ctxl, g_ctxl);
    cudaGetSymbolAddress((void**)&Ph,   g_Ph);    cudaGetSymbolAddress((void**)&Pl,   g_Pl);
    cudaGetSymbolAddress((void**)&Wah,  g_Wah);   cudaGetSymbolAddress((void**)&Wal,  g_Wal);
    cudaGetSymbolAddress((void**)&Wth,  g_Wth);   cudaGetSymbolAddress((void**)&Wtl,  g_Wtl);
    cudaGetSymbolAddress((void**)&Wbh,  g_Wbh);   cudaGetSymbolAddress((void**)&Wbl,  g_Wbl);
    cudaGetSymbolAddress((void**)&AWh,  g_AWh);   cudaGetSymbolAddress((void**)&AWl,  g_AWl);
    cudaGetSymbolAddress((void**)&WIHh, g_WIHh);  cudaGetSymbolAddress((void**)&WIHl, g_WIHl);
    cudaGetSymbolAddress((void**)&WHHh, g_WHHh);  cudaGetSymbolAddress((void**)&WHHl, g_WHHl);

    float* out = (float*)d_out;
    const int HN = M_ATOM * DDIM;
    const bool direct = (out_size >= HN + BBATCH);
    const int gA = M_ATOM / 128;  // 256

    const int SM0 = 2 * (2 * 128 * 40 + 2 * 32 * 72) * 2;   // 59392
    const int SM1 = 2 * (2 * 128 * 40 + 2 * 64 * 40) * 2;   // 61440
    cudaFuncSetAttribute(gemm_bf_k<0,1,3>, cudaFuncAttributeMaxDynamicSharedMemorySize, SM0);
    cudaFuncSetAttribute(gemm_bf_k<0,0,1>, cudaFuncAttributeMaxDynamicSharedMemorySize, SM0);
    cudaFuncSetAttribute(gemm_bf_k<0,3,2>, cudaFuncAttributeMaxDynamicSharedMemorySize, SM0);
    cudaFuncSetAttribute(gemm_gru_k,       cudaFuncAttributeMaxDynamicSharedMemorySize, SM1);

    // ---- one-time conversions ----
    pad_atom_k<<<M_ATOM, 64>>>(atom_list, A64h, A64l);
    pad_bond_k<<<M_ATOM, 32>>>(bond_list, B32h, B32l);
    conv_pad_w_k<<<64, 128>>>(atom_fc_w, Wah, Wal, FAD, 0);
    conv_pad_w_k<<<64, 128>>>(nbr_fc_w,  Wth, Wtl, FAD, 0);
    conv_pad_w_k<<<32, 128>>>(nbr_fc_w,  Wbh, Wbl, FBD, FAD);
    conv_w_k<<<192, 256>>>(attend_w,     AWh,             AWl,             3 * 16384);
    conv_w_k<<<64,  256>>>(mol_attend_w, AWh + 3 * 16384, AWl + 3 * 16384, 16384);
    conv_w_k<<<576, 256>>>(gru_wih, WIHh, WIHl, 3 * 49152);
    conv_w_k<<<576, 256>>>(gru_whh, WHHh, WHHl, 3 * 49152);

    // ---- entry GEMMs ----
    gemm_bf_k<0,1,3><<<dim3(gA, 2), 256, SM0>>>(A64h, A64l, Wah, Wal, atom_fc_b, nullptr,
                                                p_h, hh, hl, 64, DDIM);
    gemm_bf_k<0,0,1><<<dim3(gA, 2), 256, SM0>>>(A64h, A64l, Wth, Wtl, nullptr, nullptr,
                                                p_atomT, nullptr, nullptr, 64, DDIM);
    gemm_bf_k<0,0,1><<<dim3(gA, 2), 256, SM0>>>(B32h, B32l, Wbh, Wbl, nullptr, nullptr,
                                                p_bondT, nullptr, nullptr, 32, DDIM);

    // ---- radius 0 ----
    attn0_k<<<M_ATOM, 128>>>(p_h, p_atomT, p_bondT, adl, bdl, nbr_fc_b,
                             align_w, align_b, Ph, Pl, p_sumw);
    gemm_bf_k<0,3,2><<<dim3(gA, 2), 256, SM0>>>(Ph, Pl, AWh, AWl, attend_b, p_sumw,
                                                nullptr, ctxh, ctxl, DDIM, DDIM);
    gemm_gru_k<<<dim3(gA, 6, 2), 256, SM1>>>(ctxh, ctxl, hh, hl,
                                             WIHh, WIHl, WHHh, WHHl, p_gi, p_gh);
    gru_gate_k<<<(M_ATOM * 32 + 255) / 256, 256>>>(p_gi, p_gh, gru_bih, gru_bhh,
                                                   p_h, p_act, hh, hl, acth, actl, nullptr, M_ATOM);

    // ---- radii 1..R-1 ----
    for (int d = 1; d < NRAD; ++d) {
        dot2_k<<<M_ATOM, 128>>>(p_act, align_w + d * 2 * DDIM, align_w + d * 2 * DDIM + DDIM,
                                p_sc, p_sn);
        gemm_bf_k<0,0,1><<<dim3(gA, 2), 256, SM0>>>(acth, actl, AWh + (size_t)d * 16384,
                                                    AWl + (size_t)d * 16384, nullptr, nullptr,
                                                    p_P, nullptr, nullptr, DDIM, DDIM);
        attn_k<<<M_ATOM, 128>>>(p_sc, p_sn, p_P, adl, align_b + d, attend_b + d * DDIM,
                                ctxh, ctxl);
        gemm_gru_k<<<dim3(gA, 6, 2), 256, SM1>>>(ctxh, ctxl, hh, hl,
                                                 WIHh + (size_t)d * 49152, WIHl + (size_t)d * 49152,
                                                 WHHh + (size_t)d * 49152, WHHl + (size_t)d * 49152,
                                                 p_gi, p_gh);
        float* oh = (direct && d == NRAD - 1) ? out : nullptr;
        gru_gate_k<<<(M_ATOM * 32 + 255) / 256, 256>>>(p_gi, p_gh, gru_bih + d * 384,
                                                       gru_bhh + d * 384, p_h, p_act,
                                                       hh, hl, acth, actl, oh, M_ATOM);
    }

    // ---- molecule phase ----
    molsum_k<<<BBATCH, 128>>>(p_act, atom_mask, p_molf);
    gemm_bf_k<0,0,1><<<dim3(gA, 2), 256, SM0>>>(acth, actl, AWh + 3 * 16384, AWl + 3 * 16384,
                                                nullptr, nullptr, p_P, nullptr, nullptr,
                                                DDIM, DDIM);
    dot128_k<<<M_ATOM, 128>>>(p_act, mol_align_w + DDIM, p_sn);
    float* pred_dst = direct ? (out + HN) : p_pred;
    mol_k<<<BBATCH, 128>>>(p_molf, atom_mask, p_sn, p_P, mol_align_w, mol_align_b, mol_attend_b,
                           mol_gru_wih, mol_gru_whh, mol_gru_bih, mol_gru_bhh,
                           out_w, out_b, p_molf, pred_dst);

    // ---- fallback output paths ----
    if (!direct) {
        if (out_size == BBATCH) {
            copy_k<<<1, 256>>>(p_pred, out, BBATCH);
        } else {
            int n = out_size < HN ? out_size : HN;
            copy_k<<<(n + 255) / 256, 256>>>(p_h, out, n);
        }
    }
    (void)in_sizes; (void)n_in;
}